// round 3
// baseline (speedup 1.0000x reference)
#include <cuda_runtime.h>

#define BATCH 2
#define LSEQ  4096
#define HID   1024
#define DIM   64
#define NTOK  (BATCH * LSEQ)
#define LOG2GAMMA (-0.04580368961f)   /* log2(0.96875) */
#define BT 12                          /* band tiles: min excluded diff = 12*64-63 = 705 */

__device__ float g_Q[NTOK * DIM];
__device__ float g_K[NTOK * DIM];
__device__ float g_V[NTOK * DIM];

// ---------------------------------------------------------------------------
// Kernel 1: fused QKV projection + xPos epilogue.
// Block computes 32 rows x 64 cols for Q,K,V. grid = 8192/32 = 256 blocks.
// ---------------------------------------------------------------------------
__global__ __launch_bounds__(256) void qkv_kernel(
    const float* __restrict__ X,
    const float* __restrict__ Wq,
    const float* __restrict__ Wk,
    const float* __restrict__ Wv)
{
    __shared__ __align__(16) float sX[32 * 32];
    __shared__ __align__(16) float sW0[32 * 64];
    __shared__ __align__(16) float sW1[32 * 64];
    __shared__ __align__(16) float sW2[32 * 64];

    const int tid  = threadIdx.x;
    const int row0 = blockIdx.x * 32;
    const int rg   = tid >> 4;    // 0..15 -> rows 2*rg, 2*rg+1
    const int c4   = tid & 15;    // 0..15 -> cols 4*c4 .. 4*c4+3

    float acc[3][2][4];
#pragma unroll
    for (int m = 0; m < 3; m++)
#pragma unroll
        for (int r = 0; r < 2; r++)
#pragma unroll
            for (int t = 0; t < 4; t++) acc[m][r][t] = 0.f;

    const int xr = tid >> 3;          // 0..31
    const int xc = (tid & 7) << 2;    // 0..28

    for (int kc = 0; kc < HID; kc += 32) {
        // X tile: 32x32
        *(float4*)&sX[xr * 32 + xc] =
            *(const float4*)&X[(row0 + xr) * HID + kc + xc];
        // W tiles: 32x64 each, 2 float4 per thread per matrix
        {
            int wr = tid >> 4;
            int wc = (tid & 15) << 2;
            *(float4*)&sW0[wr * DIM + wc] = *(const float4*)&Wq[(kc + wr) * DIM + wc];
            *(float4*)&sW1[wr * DIM + wc] = *(const float4*)&Wk[(kc + wr) * DIM + wc];
            *(float4*)&sW2[wr * DIM + wc] = *(const float4*)&Wv[(kc + wr) * DIM + wc];
            wr += 16;
            *(float4*)&sW0[wr * DIM + wc] = *(const float4*)&Wq[(kc + wr) * DIM + wc];
            *(float4*)&sW1[wr * DIM + wc] = *(const float4*)&Wk[(kc + wr) * DIM + wc];
            *(float4*)&sW2[wr * DIM + wc] = *(const float4*)&Wv[(kc + wr) * DIM + wc];
        }
        __syncthreads();
#pragma unroll
        for (int k = 0; k < 32; k++) {
            float x0 = sX[(rg * 2) * 32 + k];
            float x1 = sX[(rg * 2 + 1) * 32 + k];
            float4 w;
            w = *(float4*)&sW0[k * DIM + c4 * 4];
            acc[0][0][0] += x0 * w.x; acc[0][0][1] += x0 * w.y;
            acc[0][0][2] += x0 * w.z; acc[0][0][3] += x0 * w.w;
            acc[0][1][0] += x1 * w.x; acc[0][1][1] += x1 * w.y;
            acc[0][1][2] += x1 * w.z; acc[0][1][3] += x1 * w.w;
            w = *(float4*)&sW1[k * DIM + c4 * 4];
            acc[1][0][0] += x0 * w.x; acc[1][0][1] += x0 * w.y;
            acc[1][0][2] += x0 * w.z; acc[1][0][3] += x0 * w.w;
            acc[1][1][0] += x1 * w.x; acc[1][1][1] += x1 * w.y;
            acc[1][1][2] += x1 * w.z; acc[1][1][3] += x1 * w.w;
            w = *(float4*)&sW2[k * DIM + c4 * 4];
            acc[2][0][0] += x0 * w.x; acc[2][0][1] += x0 * w.y;
            acc[2][0][2] += x0 * w.z; acc[2][0][3] += x0 * w.w;
            acc[2][1][0] += x1 * w.x; acc[2][1][1] += x1 * w.y;
            acc[2][1][2] += x1 * w.z; acc[2][1][3] += x1 * w.w;
        }
        __syncthreads();
    }

    // xPos epilogue: pairs (2i, 2i+1) rotated by theta_i and scaled by sv_i^(l/512)
    // (Q) or its inverse (K). Reference math in fp32; we replicate in fp32.
#pragma unroll
    for (int rr = 0; rr < 2; rr++) {
        int g = row0 + rg * 2 + rr;
        int l = g & (LSEQ - 1);
        float fl = (float)l;
#pragma unroll
        for (int pp = 0; pp < 2; pp++) {
            int i    = c4 * 2 + pp;          // pair index 0..31
            int col  = c4 * 4 + pp * 2;
            float inv_freq = powf(10000.0f, -(float)i * (1.0f / 32.0f));
            float theta = fl * inv_freq;
            float sn, cs;
            sincosf(theta, &sn, &cs);
            float sv  = ((float)(2 * i) + 25.6f) / 89.6f;   // (2i + 0.4*64)/(1.4*64)
            float scq = powf(sv, fl * (1.0f / 512.0f));
            float sck = 1.0f / scq;

            float q0 = acc[0][rr][pp * 2], q1 = acc[0][rr][pp * 2 + 1];
            float k0 = acc[1][rr][pp * 2], k1 = acc[1][rr][pp * 2 + 1];
            float cq = cs * scq, sq = sn * scq;
            float ck = cs * sck, sk = sn * sck;
            g_Q[g * DIM + col]     = q0 * cq - q1 * sq;
            g_Q[g * DIM + col + 1] = q1 * cq + q0 * sq;
            g_K[g * DIM + col]     = k0 * ck - k1 * sk;
            g_K[g * DIM + col + 1] = k1 * ck + k0 * sk;
        }
#pragma unroll
        for (int t = 0; t < 4; t++)
            g_V[g * DIM + c4 * 4 + t] = acc[2][rr][t];
    }
}

// ---------------------------------------------------------------------------
// Kernel 2: banded decay attention. One block per (batch, 64-row q-tile).
// grid = 2 * 64 = 128 blocks, 256 threads.
// Thread map: rg = tid & 31 (rows i0=rg, i1=rg+32), cg = tid >> 5 (cols 8cg..8cg+7)
//   -> every LDS in the hot loops is stride-1 across the warp (conflict-free).
// smem: Qt [d][i] 16KB, KV 16KB (K transposed, then V row-major), St [j][i] 16KB.
// ---------------------------------------------------------------------------
__global__ __launch_bounds__(256) void attn_kernel(float* __restrict__ Out)
{
    __shared__ __align__(16) float sQ[64 * 64];   // Qt: [d][i]
    __shared__ __align__(16) float sKV[64 * 64];  // Kt: [d][j], then V: [j][c]
    __shared__ __align__(16) float sS[64 * 64];   // St: [j][i]

    const int tid = threadIdx.x;
    const int b   = blockIdx.x >> 6;
    const int qt  = blockIdx.x & 63;
    const int rg  = tid & 31;     // row lane
    const int cg  = tid >> 5;     // 0..7
    const int i0  = rg;
    const int i1  = rg + 32;
    const int n0  = b * LSEQ + qt * 64;

    // Load Q tile transposed into sQ
    {
        const int token = tid >> 2;
        const int quarter = tid & 3;
#pragma unroll
        for (int t = 0; t < 4; t++) {
            int d0 = quarter * 16 + t * 4;
            float4 v = *(const float4*)&g_Q[(n0 + token) * DIM + d0];
            sQ[(d0 + 0) * 64 + token] = v.x;
            sQ[(d0 + 1) * 64 + token] = v.y;
            sQ[(d0 + 2) * 64 + token] = v.z;
            sQ[(d0 + 3) * 64 + token] = v.w;
        }
    }

    float acc[2][8];
#pragma unroll
    for (int r = 0; r < 2; r++)
#pragma unroll
        for (int t = 0; t < 8; t++) acc[r][t] = 0.f;

    // Hoisted decay factors: gamma^diff = gamma^(64*(qt-kt)) * gamma^i * gamma^-j
    const float gpi0 = exp2f((float)i0 * LOG2GAMMA);
    const float gpi1 = exp2f((float)i1 * LOG2GAMMA);
    float gmj[8];
#pragma unroll
    for (int jj = 0; jj < 8; jj++)
        gmj[jj] = exp2f(-(float)(cg * 8 + jj) * LOG2GAMMA);

    int kt0 = qt - (BT - 1);
    if (kt0 < 0) kt0 = 0;

    for (int kt = kt0; kt <= qt; kt++) {
        const int m0 = b * LSEQ + kt * 64;
        __syncthreads();  // prior iteration's reads of sKV/sS done (covers sQ first time)

        // Load K tile transposed into sKV: Kt[d][j]
        {
            const int token = tid >> 2;
            const int quarter = tid & 3;
#pragma unroll
            for (int t = 0; t < 4; t++) {
                int d0 = quarter * 16 + t * 4;
                float4 v = *(const float4*)&g_K[(m0 + token) * DIM + d0];
                sKV[(d0 + 0) * 64 + token] = v.x;
                sKV[(d0 + 1) * 64 + token] = v.y;
                sKV[(d0 + 2) * 64 + token] = v.z;
                sKV[(d0 + 3) * 64 + token] = v.w;
            }
        }
        __syncthreads();

        // S = Q K^T  (fragment: 2 rows x 8 cols per thread)
        float sf[2][8];
#pragma unroll
        for (int r = 0; r < 2; r++)
#pragma unroll
            for (int t = 0; t < 8; t++) sf[r][t] = 0.f;

#pragma unroll 16
        for (int d = 0; d < 64; d++) {
            float q0 = sQ[d * 64 + i0];
            float q1 = sQ[d * 64 + i1];
            float4 ka = *(float4*)&sKV[d * 64 + cg * 8];
            float4 kb = *(float4*)&sKV[d * 64 + cg * 8 + 4];
            sf[0][0] += q0 * ka.x; sf[0][1] += q0 * ka.y;
            sf[0][2] += q0 * ka.z; sf[0][3] += q0 * ka.w;
            sf[0][4] += q0 * kb.x; sf[0][5] += q0 * kb.y;
            sf[0][6] += q0 * kb.z; sf[0][7] += q0 * kb.w;
            sf[1][0] += q1 * ka.x; sf[1][1] += q1 * ka.y;
            sf[1][2] += q1 * ka.z; sf[1][3] += q1 * ka.w;
            sf[1][4] += q1 * kb.x; sf[1][5] += q1 * kb.y;
            sf[1][6] += q1 * kb.z; sf[1][7] += q1 * kb.w;
        }

        // Apply decay mask and store S transposed: St[j][i]
        {
            float base = exp2f((float)((qt - kt) * 64) * LOG2GAMMA);
            float d0f = base * gpi0;
            float d1f = base * gpi1;
            if (kt == qt) {
#pragma unroll
                for (int jj = 0; jj < 8; jj++) {
                    int j = cg * 8 + jj;
                    sS[j * 64 + i0] = (i0 >= j) ? sf[0][jj] * d0f * gmj[jj] : 0.f;
                    sS[j * 64 + i1] = (i1 >= j) ? sf[1][jj] * d1f * gmj[jj] : 0.f;
                }
            } else {
#pragma unroll
                for (int jj = 0; jj < 8; jj++) {
                    int j = cg * 8 + jj;
                    sS[j * 64 + i0] = sf[0][jj] * d0f * gmj[jj];
                    sS[j * 64 + i1] = sf[1][jj] * d1f * gmj[jj];
                }
            }
        }
        __syncthreads();

        // Load V tile row-major into sKV (Kt reads are done)
        {
            const int token = tid >> 2;
            const int quarter = tid & 3;
#pragma unroll
            for (int t = 0; t < 4; t++) {
                int d0 = quarter * 16 + t * 4;
                *(float4*)&sKV[token * 64 + d0] =
                    *(const float4*)&g_V[(m0 + token) * DIM + d0];
            }
        }
        __syncthreads();

        // O += S V
#pragma unroll 16
        for (int j = 0; j < 64; j++) {
            float s0 = sS[j * 64 + i0];
            float s1 = sS[j * 64 + i1];
            float4 va = *(float4*)&sKV[j * 64 + cg * 8];
            float4 vb = *(float4*)&sKV[j * 64 + cg * 8 + 4];
            acc[0][0] += s0 * va.x; acc[0][1] += s0 * va.y;
            acc[0][2] += s0 * va.z; acc[0][3] += s0 * va.w;
            acc[0][4] += s0 * vb.x; acc[0][5] += s0 * vb.y;
            acc[0][6] += s0 * vb.z; acc[0][7] += s0 * vb.w;
            acc[1][0] += s1 * va.x; acc[1][1] += s1 * va.y;
            acc[1][2] += s1 * va.z; acc[1][3] += s1 * va.w;
            acc[1][4] += s1 * vb.x; acc[1][5] += s1 * vb.y;
            acc[1][6] += s1 * vb.z; acc[1][7] += s1 * vb.w;
        }
    }

    // Write output
#pragma unroll
    for (int r = 0; r < 2; r++) {
        int n = n0 + (r == 0 ? i0 : i1);
        float4 a = make_float4(acc[r][0], acc[r][1], acc[r][2], acc[r][3]);
        float4 bv = make_float4(acc[r][4], acc[r][5], acc[r][6], acc[r][7]);
        *(float4*)&Out[n * DIM + cg * 8]     = a;
        *(float4*)&Out[n * DIM + cg * 8 + 4] = bv;
    }
}

extern "C" void kernel_launch(void* const* d_in, const int* in_sizes, int n_in,
                              void* d_out, int out_size)
{
    const float* X  = (const float*)d_in[0];
    const float* Wq = (const float*)d_in[1];
    const float* Wk = (const float*)d_in[2];
    const float* Wv = (const float*)d_in[3];
    float* Out = (float*)d_out;

    qkv_kernel<<<NTOK / 32, 256>>>(X, Wq, Wk, Wv);
    attn_kernel<<<BATCH * (LSEQ / 64), 256>>>(Out);
}

// round 7
// speedup vs baseline: 2.7857x; 2.7857x over previous
#include <cuda_runtime.h>
#include <cuda_bf16.h>
#include <stdint.h>

#define BATCH 2
#define LSEQ  4096
#define HID   1024
#define DIM   64
#define NTOK  (BATCH * LSEQ)
#define LOG2GAMMA (-0.04580368961f)   /* log2(0.96875) */

// ---------------------------------------------------------------------------
// Device globals (no dynamic allocation allowed)
// ---------------------------------------------------------------------------
__device__ float g_Q[NTOK * DIM];
__device__ float g_K[NTOK * DIM];
__device__ float g_V[NTOK * DIM];
__device__ float g_P[NTOK * DIM];                 // partial O from band half 1
__device__ __nv_bfloat16 g_Wh[192 * HID];         // W^T concat [Q|K|V], hi part
__device__ __nv_bfloat16 g_Wl[192 * HID];         // lo part
__device__ float4 g_CO[LSEQ * 32];                // xPos coefs (cq,sq,ck,sk)

// ---------------------------------------------------------------------------
// Target-portable tensor-core helpers (sm_80+: ldmatrix + mma.sync bf16)
// ---------------------------------------------------------------------------
__device__ __forceinline__ uint32_t smem_u32(const void* p) {
    uint32_t a;
    asm("{ .reg .u64 t; cvta.to.shared.u64 t, %1; cvt.u32.u64 %0, t; }"
        : "=r"(a) : "l"(p));
    return a;
}
__device__ __forceinline__ void ldsm4(uint32_t* r, uint32_t addr) {
    asm volatile("ldmatrix.sync.aligned.m8n8.x4.shared.b16 {%0,%1,%2,%3}, [%4];"
                 : "=r"(r[0]), "=r"(r[1]), "=r"(r[2]), "=r"(r[3]) : "r"(addr));
}
__device__ __forceinline__ void mma_bf16(float* d, const uint32_t* a,
                                         uint32_t b0, uint32_t b1) {
    asm volatile(
        "mma.sync.aligned.m16n8k16.row.col.f32.bf16.bf16.f32 "
        "{%0,%1,%2,%3},{%4,%5,%6,%7},{%8,%9},{%0,%1,%2,%3};"
        : "+f"(d[0]), "+f"(d[1]), "+f"(d[2]), "+f"(d[3])
        : "r"(a[0]), "r"(a[1]), "r"(a[2]), "r"(a[3]), "r"(b0), "r"(b1));
}
__device__ __forceinline__ uint32_t pack2(__nv_bfloat16 a, __nv_bfloat16 b) {
    __nv_bfloat162 p = __halves2bfloat162(a, b);
    return *(uint32_t*)&p;
}

// ---------------------------------------------------------------------------
// Prep kernel: W^T (concat 192 x 1024), split into bf16 hi/lo
// ---------------------------------------------------------------------------
__global__ __launch_bounds__(256) void prep_w(
    const float* __restrict__ Wq, const float* __restrict__ Wk,
    const float* __restrict__ Wv)
{
    int idx = blockIdx.x * 256 + threadIdx.x;   // over 192*1024
    int n = idx >> 10;
    int k = idx & 1023;
    const float* W = (n < 64) ? Wq : ((n < 128) ? Wk : Wv);
    float v = W[k * DIM + (n & 63)];
    __nv_bfloat16 h = __float2bfloat16(v);
    __nv_bfloat16 l = __float2bfloat16(v - __bfloat162float(h));
    g_Wh[n * HID + k] = h;
    g_Wl[n * HID + k] = l;
}

// ---------------------------------------------------------------------------
// Prep kernel: xPos coefficient table [l][pair i] -> (cq, sq, ck, sk)
// ---------------------------------------------------------------------------
__global__ __launch_bounds__(256) void prep_coef()
{
    int idx = blockIdx.x * 256 + threadIdx.x;   // 4096*32
    int l = idx >> 5;
    int i = idx & 31;
    float fl = (float)l;
    float inv_freq = powf(10000.0f, -(float)i * (1.0f / 32.0f));
    float sn, cs;
    sincosf(fl * inv_freq, &sn, &cs);
    float sv = ((float)(2 * i) + 25.6f) / 89.6f;
    float scq = powf(sv, fl * (1.0f / 512.0f));
    g_CO[idx] = make_float4(cs * scq, sn * scq, cs / scq, sn / scq);
}

// ---------------------------------------------------------------------------
// QKV projection via mma.sync bf16 3-term split (XhWh + XhWl + XlWh).
// Block: 64 rows x 192 cols, 8 warps (2 x 4), warp tile 32 x 48.
// K loop: 16 chunks of 64. smem tiles padded to stride 72 bf16 (144B,
// conflict-free for ldmatrix).
// ---------------------------------------------------------------------------
#define XS    72
#define OXH   0
#define OXL   (OXH + 64 * XS * 2)        /* 9216  */
#define OWH   (OXL + 64 * XS * 2)        /* 18432 */
#define OWL   (OWH + 192 * XS * 2)       /* 46080 */
#define QKV_SMEM (OWL + 192 * XS * 2)    /* 73728 */

__global__ __launch_bounds__(256, 1) void qkv_mma(const float* __restrict__ X)
{
    extern __shared__ char smem[];
    const uint32_t sb = smem_u32(smem);
    const int tid  = threadIdx.x;
    const int lane = tid & 31;
    const int wid  = tid >> 5;
    const int mr   = (wid >> 2) * 32;    // warp row base (0 or 32)
    const int nc   = (wid & 3) * 48;     // warp col base
    const int row0 = blockIdx.x * 64;

    float acc[2][6][4];
#pragma unroll
    for (int a = 0; a < 2; a++)
#pragma unroll
        for (int b = 0; b < 6; b++)
#pragma unroll
            for (int c = 0; c < 4; c++) acc[a][b][c] = 0.f;

    for (int ch = 0; ch < 16; ch++) {
        const int kc = ch * 64;
        // --- X tile 64x64 fp32 -> bf16 hi/lo ---
#pragma unroll
        for (int it = 0; it < 4; it++) {
            int s = it * 256 + tid;          // 1024 float4 slots
            int r = s >> 4;
            int c = (s & 15) << 2;
            float4 x = *(const float4*)&X[(row0 + r) * HID + kc + c];
            __nv_bfloat16 hx = __float2bfloat16(x.x);
            __nv_bfloat16 hy = __float2bfloat16(x.y);
            __nv_bfloat16 hz = __float2bfloat16(x.z);
            __nv_bfloat16 hw = __float2bfloat16(x.w);
            uint2 hv = make_uint2(pack2(hx, hy), pack2(hz, hw));
            uint2 lv = make_uint2(
                pack2(__float2bfloat16(x.x - __bfloat162float(hx)),
                      __float2bfloat16(x.y - __bfloat162float(hy))),
                pack2(__float2bfloat16(x.z - __bfloat162float(hz)),
                      __float2bfloat16(x.w - __bfloat162float(hw))));
            uint32_t off = (uint32_t)(r * XS + c) * 2;
            *(uint2*)(smem + OXH + off) = hv;
            *(uint2*)(smem + OXL + off) = lv;
        }
        // --- W tiles 192x64 bf16 hi/lo (pre-split) ---
#pragma unroll
        for (int it = 0; it < 6; it++) {
            int s = it * 256 + tid;          // 1536 uint4 slots
            int n = s >> 3;
            int c8 = (s & 7) << 3;
            uint4 hv = *(const uint4*)&g_Wh[n * HID + kc + c8];
            uint4 lv = *(const uint4*)&g_Wl[n * HID + kc + c8];
            uint32_t off = (uint32_t)(n * XS + c8) * 2;
            *(uint4*)(smem + OWH + off) = hv;
            *(uint4*)(smem + OWL + off) = lv;
        }
        __syncthreads();

#pragma unroll
        for (int ks = 0; ks < 4; ks++) {
            const int lrow = lane & 15;
            const int lcol = ks * 16 + ((lane >> 4) << 3);
            uint32_t ah[2][4], al[2][4], bh[3][4], bl[3][4];
#pragma unroll
            for (int am = 0; am < 2; am++) {
                uint32_t off = (uint32_t)((mr + am * 16 + lrow) * XS + lcol) * 2;
                ldsm4(ah[am], sb + OXH + off);
                ldsm4(al[am], sb + OXL + off);
            }
#pragma unroll
            for (int nf = 0; nf < 3; nf++) {
                uint32_t off = (uint32_t)((nc + nf * 16 + lrow) * XS + lcol) * 2;
                ldsm4(bh[nf], sb + OWH + off);
                ldsm4(bl[nf], sb + OWL + off);
            }
#pragma unroll
            for (int am = 0; am < 2; am++)
#pragma unroll
                for (int nf = 0; nf < 3; nf++) {
                    // x4 regs: {0,2} = n-group 0 (k0-7,k8-15), {1,3} = n-group 1
                    mma_bf16(acc[am][nf * 2],     ah[am], bh[nf][0], bh[nf][2]);
                    mma_bf16(acc[am][nf * 2],     ah[am], bl[nf][0], bl[nf][2]);
                    mma_bf16(acc[am][nf * 2],     al[am], bh[nf][0], bh[nf][2]);
                    mma_bf16(acc[am][nf * 2 + 1], ah[am], bh[nf][1], bh[nf][3]);
                    mma_bf16(acc[am][nf * 2 + 1], ah[am], bl[nf][1], bl[nf][3]);
                    mma_bf16(acc[am][nf * 2 + 1], al[am], bh[nf][1], bh[nf][3]);
                }
        }
        __syncthreads();
    }

    // --- Epilogue: xPos for Q/K, plain store for V ---
    const int r4 = lane >> 2;
    const int c2 = (lane & 3) * 2;
#pragma unroll
    for (int am = 0; am < 2; am++) {
#pragma unroll
        for (int h2 = 0; h2 < 2; h2++) {
            int g = row0 + mr + am * 16 + h2 * 8 + r4;
            int l = g & (LSEQ - 1);
#pragma unroll
            for (int nf = 0; nf < 6; nf++) {
                int col0 = nc + nf * 8;
                int mat  = col0 >> 6;
                int lcol = (col0 & 63) + c2;
                float v0 = acc[am][nf][h2 * 2 + 0];
                float v1 = acc[am][nf][h2 * 2 + 1];
                if (mat == 0) {
                    float4 co = g_CO[l * 32 + (lcol >> 1)];
                    *(float2*)&g_Q[g * DIM + lcol] =
                        make_float2(v0 * co.x - v1 * co.y,
                                    v1 * co.x + v0 * co.y);
                } else if (mat == 1) {
                    float4 co = g_CO[l * 32 + (lcol >> 1)];
                    *(float2*)&g_K[g * DIM + lcol] =
                        make_float2(v0 * co.z - v1 * co.w,
                                    v1 * co.z + v0 * co.w);
                } else {
                    *(float2*)&g_V[g * DIM + lcol] = make_float2(v0, v1);
                }
            }
        }
    }
}

// ---------------------------------------------------------------------------
// Banded decay attention, band split across 2 blocks per (b, qt).
// p=0: kt in [qt-5, qt] -> Out;  p=1: kt in [qt-11, qt-6] -> g_P partial.
// grid = 2 * 2 * 64 = 256 blocks, 256 threads.
// ---------------------------------------------------------------------------
__global__ __launch_bounds__(256) void attn_kernel(float* __restrict__ Out)
{
    __shared__ __align__(16) float sQ[64 * 64];   // Qt: [d][i]
    __shared__ __align__(16) float sKV[64 * 64];  // Kt: [d][j], then V: [j][c]
    __shared__ __align__(16) float sS[64 * 64];   // St: [j][i]

    const int tid = threadIdx.x;
    const int p   = blockIdx.x >> 7;
    const int b   = (blockIdx.x >> 6) & 1;
    const int qt  = blockIdx.x & 63;
    const int rg  = tid & 31;
    const int cg  = tid >> 5;
    const int i0  = rg;
    const int i1  = rg + 32;
    const int n0  = b * LSEQ + qt * 64;

    float* __restrict__ dst = p ? g_P : Out;

    int kt0, kt1;
    if (p == 0) { kt0 = qt - 5;  if (kt0 < 0) kt0 = 0; kt1 = qt; }
    else        { kt0 = qt - 11; if (kt0 < 0) kt0 = 0; kt1 = qt - 6; }

    if (kt1 < kt0) {   // empty band half: write zeros (keeps combine simple)
        float4 z = make_float4(0.f, 0.f, 0.f, 0.f);
        for (int t = tid; t < 64 * DIM / 4; t += 256)
            ((float4*)&dst[(size_t)n0 * DIM])[t] = z;
        return;
    }

    // Load Q tile transposed into sQ
    {
        const int token = tid >> 2;
        const int quarter = tid & 3;
#pragma unroll
        for (int t = 0; t < 4; t++) {
            int d0 = quarter * 16 + t * 4;
            float4 v = *(const float4*)&g_Q[(size_t)(n0 + token) * DIM + d0];
            sQ[(d0 + 0) * 64 + token] = v.x;
            sQ[(d0 + 1) * 64 + token] = v.y;
            sQ[(d0 + 2) * 64 + token] = v.z;
            sQ[(d0 + 3) * 64 + token] = v.w;
        }
    }

    float acc[2][8];
#pragma unroll
    for (int r = 0; r < 2; r++)
#pragma unroll
        for (int t = 0; t < 8; t++) acc[r][t] = 0.f;

    const float gpi0 = exp2f((float)i0 * LOG2GAMMA);
    const float gpi1 = exp2f((float)i1 * LOG2GAMMA);
    float gmj[8];
#pragma unroll
    for (int jj = 0; jj < 8; jj++)
        gmj[jj] = exp2f(-(float)(cg * 8 + jj) * LOG2GAMMA);

    for (int kt = kt0; kt <= kt1; kt++) {
        const int m0 = b * LSEQ + kt * 64;
        __syncthreads();

        // K tile transposed: Kt[d][j]
        {
            const int token = tid >> 2;
            const int quarter = tid & 3;
#pragma unroll
            for (int t = 0; t < 4; t++) {
                int d0 = quarter * 16 + t * 4;
                float4 v = *(const float4*)&g_K[(size_t)(m0 + token) * DIM + d0];
                sKV[(d0 + 0) * 64 + token] = v.x;
                sKV[(d0 + 1) * 64 + token] = v.y;
                sKV[(d0 + 2) * 64 + token] = v.z;
                sKV[(d0 + 3) * 64 + token] = v.w;
            }
        }
        __syncthreads();

        float sf[2][8];
#pragma unroll
        for (int r = 0; r < 2; r++)
#pragma unroll
            for (int t = 0; t < 8; t++) sf[r][t] = 0.f;

#pragma unroll 16
        for (int d = 0; d < 64; d++) {
            float q0 = sQ[d * 64 + i0];
            float q1 = sQ[d * 64 + i1];
            float4 ka = *(float4*)&sKV[d * 64 + cg * 8];
            float4 kb = *(float4*)&sKV[d * 64 + cg * 8 + 4];
            sf[0][0] += q0 * ka.x; sf[0][1] += q0 * ka.y;
            sf[0][2] += q0 * ka.z; sf[0][3] += q0 * ka.w;
            sf[0][4] += q0 * kb.x; sf[0][5] += q0 * kb.y;
            sf[0][6] += q0 * kb.z; sf[0][7] += q0 * kb.w;
            sf[1][0] += q1 * ka.x; sf[1][1] += q1 * ka.y;
            sf[1][2] += q1 * ka.z; sf[1][3] += q1 * ka.w;
            sf[1][4] += q1 * kb.x; sf[1][5] += q1 * kb.y;
            sf[1][6] += q1 * kb.z; sf[1][7] += q1 * kb.w;
        }

        {
            float base = exp2f((float)((qt - kt) * 64) * LOG2GAMMA);
            float d0f = base * gpi0;
            float d1f = base * gpi1;
            if (kt == qt) {
#pragma unroll
                for (int jj = 0; jj < 8; jj++) {
                    int j = cg * 8 + jj;
                    sS[j * 64 + i0] = (i0 >= j) ? sf[0][jj] * d0f * gmj[jj] : 0.f;
                    sS[j * 64 + i1] = (i1 >= j) ? sf[1][jj] * d1f * gmj[jj] : 0.f;
                }
            } else {
#pragma unroll
                for (int jj = 0; jj < 8; jj++) {
                    int j = cg * 8 + jj;
                    sS[j * 64 + i0] = sf[0][jj] * d0f * gmj[jj];
                    sS[j * 64 + i1] = sf[1][jj] * d1f * gmj[jj];
                }
            }
        }
        __syncthreads();

        // V tile row-major into sKV
        {
            const int token = tid >> 2;
            const int quarter = tid & 3;
#pragma unroll
            for (int t = 0; t < 4; t++) {
                int d0 = quarter * 16 + t * 4;
                *(float4*)&sKV[token * 64 + d0] =
                    *(const float4*)&g_V[(size_t)(m0 + token) * DIM + d0];
            }
        }
        __syncthreads();

#pragma unroll 16
        for (int j = 0; j < 64; j++) {
            float s0 = sS[j * 64 + i0];
            float s1 = sS[j * 64 + i1];
            float4 va = *(float4*)&sKV[j * 64 + cg * 8];
            float4 vb = *(float4*)&sKV[j * 64 + cg * 8 + 4];
            acc[0][0] += s0 * va.x; acc[0][1] += s0 * va.y;
            acc[0][2] += s0 * va.z; acc[0][3] += s0 * va.w;
            acc[0][4] += s0 * vb.x; acc[0][5] += s0 * vb.y;
            acc[0][6] += s0 * vb.z; acc[0][7] += s0 * vb.w;
            acc[1][0] += s1 * va.x; acc[1][1] += s1 * va.y;
            acc[1][2] += s1 * va.z; acc[1][3] += s1 * va.w;
            acc[1][4] += s1 * vb.x; acc[1][5] += s1 * vb.y;
            acc[1][6] += s1 * vb.z; acc[1][7] += s1 * vb.w;
        }
    }

#pragma unroll
    for (int r = 0; r < 2; r++) {
        int n = n0 + (r == 0 ? i0 : i1);
        float4 a = make_float4(acc[r][0], acc[r][1], acc[r][2], acc[r][3]);
        float4 bv = make_float4(acc[r][4], acc[r][5], acc[r][6], acc[r][7]);
        *(float4*)&dst[(size_t)n * DIM + cg * 8]     = a;
        *(float4*)&dst[(size_t)n * DIM + cg * 8 + 4] = bv;
    }
}

// ---------------------------------------------------------------------------
// Combine: Out += partial (band half 1)
// ---------------------------------------------------------------------------
__global__ __launch_bounds__(256) void combine_kernel(float* __restrict__ Out)
{
    int i = blockIdx.x * 256 + threadIdx.x;     // float4 index, NTOK*DIM/4 total
    float4 a = ((float4*)Out)[i];
    float4 q = ((const float4*)g_P)[i];
    a.x += q.x; a.y += q.y; a.z += q.z; a.w += q.w;
    ((float4*)Out)[i] = a;
}

// ---------------------------------------------------------------------------
extern "C" void kernel_launch(void* const* d_in, const int* in_sizes, int n_in,
                              void* d_out, int out_size)
{
    const float* X  = (const float*)d_in[0];
    const float* Wq = (const float*)d_in[1];
    const float* Wk = (const float*)d_in[2];
    const float* Wv = (const float*)d_in[3];
    float* Out = (float*)d_out;

    cudaFuncSetAttribute(qkv_mma, cudaFuncAttributeMaxDynamicSharedMemorySize,
                         QKV_SMEM);

    prep_w<<<192 * HID / 256, 256>>>(Wq, Wk, Wv);
    prep_coef<<<LSEQ * 32 / 256, 256>>>();
    qkv_mma<<<NTOK / 64, 256, QKV_SMEM>>>(X);
    attn_kernel<<<2 * BATCH * (LSEQ / 64), 256>>>(Out);
    combine_kernel<<<NTOK * DIM / 4 / 256, 256>>>(Out);
}

// round 8
// speedup vs baseline: 4.4776x; 1.6073x over previous
#include <cuda_runtime.h>
#include <cuda_bf16.h>
#include <stdint.h>

#define BATCH 2
#define LSEQ  4096
#define HID   1024
#define DIM   64
#define NTOK  (BATCH * LSEQ)
#define LOG2GAMMA (-0.04580368961f)   /* log2(0.96875) */

// ---------------------------------------------------------------------------
// Device globals
// ---------------------------------------------------------------------------
__device__ __nv_bfloat16 g_Qh[NTOK * DIM];
__device__ __nv_bfloat16 g_Ql[NTOK * DIM];
__device__ __nv_bfloat16 g_Kh[NTOK * DIM];
__device__ __nv_bfloat16 g_Kl[NTOK * DIM];
__device__ __nv_bfloat16 g_Vth[NTOK * DIM];       // per-64-tile transposed [t][d][tok]
__device__ __nv_bfloat16 g_Vtl[NTOK * DIM];
__device__ float g_P[NTOK * DIM];                 // partial O from band half 1
__device__ __nv_bfloat16 g_Wh[192 * HID];         // W^T concat [Q|K|V], hi part
__device__ __nv_bfloat16 g_Wl[192 * HID];         // lo part
__device__ float4 g_CO[LSEQ * 32];                // xPos coefs (cq,sq,ck,sk)

// ---------------------------------------------------------------------------
// Tensor-core helpers (sm_80+ portable: ldmatrix + mma.sync bf16)
// ---------------------------------------------------------------------------
__device__ __forceinline__ uint32_t smem_u32(const void* p) {
    uint32_t a;
    asm("{ .reg .u64 t; cvta.to.shared.u64 t, %1; cvt.u32.u64 %0, t; }"
        : "=r"(a) : "l"(p));
    return a;
}
__device__ __forceinline__ void ldsm4(uint32_t* r, uint32_t addr) {
    asm volatile("ldmatrix.sync.aligned.m8n8.x4.shared.b16 {%0,%1,%2,%3}, [%4];"
                 : "=r"(r[0]), "=r"(r[1]), "=r"(r[2]), "=r"(r[3]) : "r"(addr));
}
__device__ __forceinline__ void mma_bf16(float* d, const uint32_t* a,
                                         uint32_t b0, uint32_t b1) {
    asm volatile(
        "mma.sync.aligned.m16n8k16.row.col.f32.bf16.bf16.f32 "
        "{%0,%1,%2,%3},{%4,%5,%6,%7},{%8,%9},{%0,%1,%2,%3};"
        : "+f"(d[0]), "+f"(d[1]), "+f"(d[2]), "+f"(d[3])
        : "r"(a[0]), "r"(a[1]), "r"(a[2]), "r"(a[3]), "r"(b0), "r"(b1));
}
__device__ __forceinline__ uint32_t pack2(__nv_bfloat16 a, __nv_bfloat16 b) {
    __nv_bfloat162 p = __halves2bfloat162(a, b);
    return *(uint32_t*)&p;
}

// ---------------------------------------------------------------------------
// Prep: W^T concat (192 x 1024) split into bf16 hi/lo
// ---------------------------------------------------------------------------
__global__ __launch_bounds__(256) void prep_w(
    const float* __restrict__ Wq, const float* __restrict__ Wk,
    const float* __restrict__ Wv)
{
    int idx = blockIdx.x * 256 + threadIdx.x;
    int n = idx >> 10;
    int k = idx & 1023;
    const float* W = (n < 64) ? Wq : ((n < 128) ? Wk : Wv);
    float v = W[k * DIM + (n & 63)];
    __nv_bfloat16 h = __float2bfloat16(v);
    __nv_bfloat16 l = __float2bfloat16(v - __bfloat162float(h));
    g_Wh[n * HID + k] = h;
    g_Wl[n * HID + k] = l;
}

// ---------------------------------------------------------------------------
// Prep: xPos coefficient table [l][pair i] -> (cq, sq, ck, sk)
// ---------------------------------------------------------------------------
__global__ __launch_bounds__(256) void prep_coef()
{
    int idx = blockIdx.x * 256 + threadIdx.x;
    int l = idx >> 5;
    int i = idx & 31;
    float fl = (float)l;
    float inv_freq = powf(10000.0f, -(float)i * (1.0f / 32.0f));
    float sn, cs;
    sincosf(fl * inv_freq, &sn, &cs);
    float sv = ((float)(2 * i) + 25.6f) / 89.6f;
    float scq = powf(sv, fl * (1.0f / 512.0f));
    g_CO[idx] = make_float4(cs * scq, sn * scq, cs / scq, sn / scq);
}

// ---------------------------------------------------------------------------
// QKV projection via mma.sync bf16 3-term split.
// Block 64 rows x 192 cols, 8 warps, warp tile 32 x 48; K chunks of 64.
// Epilogue: xPos + hi/lo bf16 split for Q/K; V stored transposed hi/lo.
// ---------------------------------------------------------------------------
#define XS    72
#define OXH   0
#define OXL   (OXH + 64 * XS * 2)
#define OWH   (OXL + 64 * XS * 2)
#define OWL   (OWH + 192 * XS * 2)
#define QKV_SMEM (OWL + 192 * XS * 2)    /* 73728 */

__global__ __launch_bounds__(256, 1) void qkv_mma(const float* __restrict__ X)
{
    extern __shared__ char smem[];
    const uint32_t sb = smem_u32(smem);
    const int tid  = threadIdx.x;
    const int lane = tid & 31;
    const int wid  = tid >> 5;
    const int mr   = (wid >> 2) * 32;
    const int nc   = (wid & 3) * 48;
    const int row0 = blockIdx.x * 64;

    float acc[2][6][4];
#pragma unroll
    for (int a = 0; a < 2; a++)
#pragma unroll
        for (int b = 0; b < 6; b++)
#pragma unroll
            for (int c = 0; c < 4; c++) acc[a][b][c] = 0.f;

    for (int ch = 0; ch < 16; ch++) {
        const int kc = ch * 64;
#pragma unroll
        for (int it = 0; it < 4; it++) {
            int s = it * 256 + tid;
            int r = s >> 4;
            int c = (s & 15) << 2;
            float4 x = *(const float4*)&X[(row0 + r) * HID + kc + c];
            __nv_bfloat16 hx = __float2bfloat16(x.x);
            __nv_bfloat16 hy = __float2bfloat16(x.y);
            __nv_bfloat16 hz = __float2bfloat16(x.z);
            __nv_bfloat16 hw = __float2bfloat16(x.w);
            uint2 hv = make_uint2(pack2(hx, hy), pack2(hz, hw));
            uint2 lv = make_uint2(
                pack2(__float2bfloat16(x.x - __bfloat162float(hx)),
                      __float2bfloat16(x.y - __bfloat162float(hy))),
                pack2(__float2bfloat16(x.z - __bfloat162float(hz)),
                      __float2bfloat16(x.w - __bfloat162float(hw))));
            uint32_t off = (uint32_t)(r * XS + c) * 2;
            *(uint2*)(smem + OXH + off) = hv;
            *(uint2*)(smem + OXL + off) = lv;
        }
#pragma unroll
        for (int it = 0; it < 6; it++) {
            int s = it * 256 + tid;
            int n = s >> 3;
            int c8 = (s & 7) << 3;
            uint4 hv = *(const uint4*)&g_Wh[n * HID + kc + c8];
            uint4 lv = *(const uint4*)&g_Wl[n * HID + kc + c8];
            uint32_t off = (uint32_t)(n * XS + c8) * 2;
            *(uint4*)(smem + OWH + off) = hv;
            *(uint4*)(smem + OWL + off) = lv;
        }
        __syncthreads();

#pragma unroll
        for (int ks = 0; ks < 4; ks++) {
            const int lrow = lane & 15;
            const int lcol = ks * 16 + ((lane >> 4) << 3);
            uint32_t ah[2][4], al[2][4], bh[3][4], bl[3][4];
#pragma unroll
            for (int am = 0; am < 2; am++) {
                uint32_t off = (uint32_t)((mr + am * 16 + lrow) * XS + lcol) * 2;
                ldsm4(ah[am], sb + OXH + off);
                ldsm4(al[am], sb + OXL + off);
            }
#pragma unroll
            for (int nf = 0; nf < 3; nf++) {
                uint32_t off = (uint32_t)((nc + nf * 16 + lrow) * XS + lcol) * 2;
                ldsm4(bh[nf], sb + OWH + off);
                ldsm4(bl[nf], sb + OWL + off);
            }
#pragma unroll
            for (int am = 0; am < 2; am++)
#pragma unroll
                for (int nf = 0; nf < 3; nf++) {
                    mma_bf16(acc[am][nf * 2],     ah[am], bh[nf][0], bh[nf][2]);
                    mma_bf16(acc[am][nf * 2],     ah[am], bl[nf][0], bl[nf][2]);
                    mma_bf16(acc[am][nf * 2],     al[am], bh[nf][0], bh[nf][2]);
                    mma_bf16(acc[am][nf * 2 + 1], ah[am], bh[nf][1], bh[nf][3]);
                    mma_bf16(acc[am][nf * 2 + 1], ah[am], bl[nf][1], bl[nf][3]);
                    mma_bf16(acc[am][nf * 2 + 1], al[am], bh[nf][1], bh[nf][3]);
                }
        }
        __syncthreads();
    }

    // --- Epilogue ---
    const int r4 = lane >> 2;
    const int c2 = (lane & 3) * 2;
#pragma unroll
    for (int am = 0; am < 2; am++) {
#pragma unroll
        for (int h2 = 0; h2 < 2; h2++) {
            int g = row0 + mr + am * 16 + h2 * 8 + r4;
            int l = g & (LSEQ - 1);
#pragma unroll
            for (int nf = 0; nf < 6; nf++) {
                int col0 = nc + nf * 8;
                int mat  = col0 >> 6;
                int lcol = (col0 & 63) + c2;
                float v0 = acc[am][nf][h2 * 2 + 0];
                float v1 = acc[am][nf][h2 * 2 + 1];
                if (mat == 0) {
                    float4 co = g_CO[l * 32 + (lcol >> 1)];
                    float o0 = v0 * co.x - v1 * co.y;
                    float o1 = v1 * co.x + v0 * co.y;
                    __nv_bfloat16 h0 = __float2bfloat16(o0);
                    __nv_bfloat16 h1 = __float2bfloat16(o1);
                    *(uint32_t*)&g_Qh[g * DIM + lcol] = pack2(h0, h1);
                    *(uint32_t*)&g_Ql[g * DIM + lcol] =
                        pack2(__float2bfloat16(o0 - __bfloat162float(h0)),
                              __float2bfloat16(o1 - __bfloat162float(h1)));
                } else if (mat == 1) {
                    float4 co = g_CO[l * 32 + (lcol >> 1)];
                    float o0 = v0 * co.z - v1 * co.w;
                    float o1 = v1 * co.z + v0 * co.w;
                    __nv_bfloat16 h0 = __float2bfloat16(o0);
                    __nv_bfloat16 h1 = __float2bfloat16(o1);
                    *(uint32_t*)&g_Kh[g * DIM + lcol] = pack2(h0, h1);
                    *(uint32_t*)&g_Kl[g * DIM + lcol] =
                        pack2(__float2bfloat16(o0 - __bfloat162float(h0)),
                              __float2bfloat16(o1 - __bfloat162float(h1)));
                } else {
                    int t = g >> 6, tok = g & 63;
                    __nv_bfloat16 h0 = __float2bfloat16(v0);
                    __nv_bfloat16 h1 = __float2bfloat16(v1);
                    g_Vth[t * 4096 + lcol * 64 + tok]       = h0;
                    g_Vth[t * 4096 + (lcol + 1) * 64 + tok] = h1;
                    g_Vtl[t * 4096 + lcol * 64 + tok] =
                        __float2bfloat16(v0 - __bfloat162float(h0));
                    g_Vtl[t * 4096 + (lcol + 1) * 64 + tok] =
                        __float2bfloat16(v1 - __bfloat162float(h1));
                }
            }
        }
    }
}

// ---------------------------------------------------------------------------
// Banded decay attention on tensor cores. Band = 8 tiles, split 4+4 over
// p=0 (recent -> Out) / p=1 (older -> g_P). Grid 256, 8 warps.
// Warp (rg = wid&3, jc = wid>>2): rows rg*16..+15, j-window jc*32..+31.
// S = QK^T via 3-term bf16; decay+mask in C-frags; frag-direct hi/lo convert
// to A-operand; O += S V via 3-term bf16 on transposed V tiles. Pairs
// (w, w+4) reduce partial O through smem at the end.
// ---------------------------------------------------------------------------
#define AS     72
#define OQH_A  0
#define OQL_A  (OQH_A + 64 * AS * 2)
#define OKH_A  (OQL_A + 64 * AS * 2)
#define OKL_A  (OKH_A + 64 * AS * 2)
#define OVH_A  (OKL_A + 64 * AS * 2)
#define OVL_A  (OVH_A + 64 * AS * 2)
#define ATTN_SMEM (OVL_A + 64 * AS * 2)   /* 55296 */
#define RED_S  68                          /* fp32 reduction stride */

__global__ __launch_bounds__(256) void attn_mma(float* __restrict__ Out)
{
    extern __shared__ char sm[];
    const uint32_t sb = smem_u32(sm);
    const int tid  = threadIdx.x;
    const int lane = tid & 31;
    const int wid  = tid >> 5;
    const int rg   = wid & 3;      // row-group: rows rg*16 .. +15
    const int jc   = wid >> 2;     // j half: jc*32 .. +31
    const int p    = blockIdx.x >> 7;
    const int b    = (blockIdx.x >> 6) & 1;
    const int qt   = blockIdx.x & 63;
    const int n0   = b * LSEQ + qt * 64;

    float* __restrict__ dst = p ? g_P : Out;

    int kt0, kt1;
    if (p == 0) { kt0 = qt - 3; if (kt0 < 0) kt0 = 0; kt1 = qt; }
    else        { kt0 = qt - 7; if (kt0 < 0) kt0 = 0; kt1 = qt - 4; }

    if (kt1 < kt0) {
        float4 z = make_float4(0.f, 0.f, 0.f, 0.f);
        for (int t = tid; t < 64 * DIM / 4; t += 256)
            ((float4*)&dst[(size_t)n0 * DIM])[t] = z;
        return;
    }

    // Load Q hi/lo tiles (row-major, stride AS)
#pragma unroll
    for (int it = 0; it < 2; it++) {
        int s = it * 256 + tid;             // 512 uint4 slots
        int r = s >> 3, c8 = (s & 7) << 3;
        uint32_t off = (uint32_t)(r * AS + c8) * 2;
        *(uint4*)(sm + OQH_A + off) = *(const uint4*)&g_Qh[(size_t)(n0 + r) * DIM + c8];
        *(uint4*)(sm + OQL_A + off) = *(const uint4*)&g_Ql[(size_t)(n0 + r) * DIM + c8];
    }

    float oacc[8][4];
#pragma unroll
    for (int d = 0; d < 8; d++)
#pragma unroll
        for (int c = 0; c < 4; c++) oacc[d][c] = 0.f;

    const int r0 = rg * 16 + (lane >> 2);
    const float gi0 = exp2f((float)r0 * LOG2GAMMA);
    const float gi1 = exp2f((float)(r0 + 8) * LOG2GAMMA);
    float gj[4][2];
#pragma unroll
    for (int jt = 0; jt < 4; jt++) {
        int j = jc * 32 + jt * 8 + ((lane & 3) << 1);
        gj[jt][0] = exp2f(-(float)j * LOG2GAMMA);
        gj[jt][1] = exp2f(-(float)(j + 1) * LOG2GAMMA);
    }

    const int lrow = lane & 15;
    const int lcg  = (lane >> 4) << 3;

    for (int kt = kt0; kt <= kt1; kt++) {
        const int m0 = b * LSEQ + kt * 64;
        const int tile = m0 >> 6;
        __syncthreads();
        // Load K hi/lo (row-major) + Vt hi/lo (d-major) tiles
#pragma unroll
        for (int it = 0; it < 2; it++) {
            int s = it * 256 + tid;
            int r = s >> 3, c8 = (s & 7) << 3;
            uint32_t off = (uint32_t)(r * AS + c8) * 2;
            *(uint4*)(sm + OKH_A + off) = *(const uint4*)&g_Kh[(size_t)(m0 + r) * DIM + c8];
            *(uint4*)(sm + OKL_A + off) = *(const uint4*)&g_Kl[(size_t)(m0 + r) * DIM + c8];
            *(uint4*)(sm + OVH_A + off) = *(const uint4*)&g_Vth[(size_t)tile * 4096 + r * 64 + c8];
            *(uint4*)(sm + OVL_A + off) = *(const uint4*)&g_Vtl[(size_t)tile * 4096 + r * 64 + c8];
        }
        __syncthreads();

        // ---- S = Q K^T (3-term) ----
        float sfrag[4][4];
#pragma unroll
        for (int jt = 0; jt < 4; jt++)
#pragma unroll
            for (int c = 0; c < 4; c++) sfrag[jt][c] = 0.f;

#pragma unroll
        for (int ks = 0; ks < 4; ks++) {
            uint32_t aoff = (uint32_t)((rg * 16 + lrow) * AS + ks * 16 + lcg) * 2;
            uint32_t ah[4], al[4];
            ldsm4(ah, sb + OQH_A + aoff);
            ldsm4(al, sb + OQL_A + aoff);
            uint32_t bh[2][4], bl[2][4];
#pragma unroll
            for (int jg = 0; jg < 2; jg++) {
                uint32_t boff = (uint32_t)((jc * 32 + jg * 16 + lrow) * AS + ks * 16 + lcg) * 2;
                ldsm4(bh[jg], sb + OKH_A + boff);
                ldsm4(bl[jg], sb + OKL_A + boff);
            }
#pragma unroll
            for (int jt = 0; jt < 4; jt++) {
                int jg = jt >> 1, sel = jt & 1;
                uint32_t b0h = bh[jg][sel], b1h = bh[jg][sel + 2];
                uint32_t b0l = bl[jg][sel], b1l = bl[jg][sel + 2];
                mma_bf16(sfrag[jt], ah, b0h, b1h);
                mma_bf16(sfrag[jt], ah, b0l, b1l);
                mma_bf16(sfrag[jt], al, b0h, b1h);
            }
        }

        // ---- decay + mask + frag-direct hi/lo conversion ----
        const float basekt = exp2f((float)((qt - kt) * 64) * LOG2GAMMA);
        uint32_t shh[2][4], sll[2][4];
#pragma unroll
        for (int jt = 0; jt < 4; jt++) {
            float w0 = basekt * gj[jt][0];
            float w1 = basekt * gj[jt][1];
            float v0 = sfrag[jt][0] * gi0 * w0;
            float v1 = sfrag[jt][1] * gi0 * w1;
            float v2 = sfrag[jt][2] * gi1 * w0;
            float v3 = sfrag[jt][3] * gi1 * w1;
            if (kt == qt) {
                int j0 = jc * 32 + jt * 8 + ((lane & 3) << 1);
                if (r0 < j0)         v0 = 0.f;
                if (r0 < j0 + 1)     v1 = 0.f;
                if (r0 + 8 < j0)     v2 = 0.f;
                if (r0 + 8 < j0 + 1) v3 = 0.f;
            }
            __nv_bfloat16 h0 = __float2bfloat16(v0);
            __nv_bfloat16 h1 = __float2bfloat16(v1);
            __nv_bfloat16 h2 = __float2bfloat16(v2);
            __nv_bfloat16 h3 = __float2bfloat16(v3);
            int ks2 = jt >> 1, odd = jt & 1;
            shh[ks2][odd * 2 + 0] = pack2(h0, h1);
            shh[ks2][odd * 2 + 1] = pack2(h2, h3);
            sll[ks2][odd * 2 + 0] =
                pack2(__float2bfloat16(v0 - __bfloat162float(h0)),
                      __float2bfloat16(v1 - __bfloat162float(h1)));
            sll[ks2][odd * 2 + 1] =
                pack2(__float2bfloat16(v2 - __bfloat162float(h2)),
                      __float2bfloat16(v3 - __bfloat162float(h3)));
        }

        // ---- O += S V (3-term), B from transposed V tiles ----
#pragma unroll
        for (int ks2 = 0; ks2 < 2; ks2++) {
            uint32_t vbh[4][4], vbl[4][4];
#pragma unroll
            for (int dg = 0; dg < 4; dg++) {
                uint32_t voff = (uint32_t)((dg * 16 + lrow) * AS + jc * 32 + ks2 * 16 + lcg) * 2;
                ldsm4(vbh[dg], sb + OVH_A + voff);
                ldsm4(vbl[dg], sb + OVL_A + voff);
            }
#pragma unroll
            for (int dt = 0; dt < 8; dt++) {
                int dg = dt >> 1, sel = dt & 1;
                uint32_t b0h = vbh[dg][sel], b1h = vbh[dg][sel + 2];
                uint32_t b0l = vbl[dg][sel], b1l = vbl[dg][sel + 2];
                mma_bf16(oacc[dt], shh[ks2], b0h, b1h);
                mma_bf16(oacc[dt], sll[ks2], b0h, b1h);
                mma_bf16(oacc[dt], shh[ks2], b0l, b1l);
            }
        }
    }

    // ---- pair reduction (w, w+4) over smem, then store ----
    __syncthreads();
    float* red = (float*)sm;                 // [64][RED_S] fp32, reuses Q area
    const int c2 = (lane & 3) << 1;
    if (jc == 1) {
#pragma unroll
        for (int dt = 0; dt < 8; dt++) {
            int d = dt * 8 + c2;
            red[r0 * RED_S + d]           = oacc[dt][0];
            red[r0 * RED_S + d + 1]       = oacc[dt][1];
            red[(r0 + 8) * RED_S + d]     = oacc[dt][2];
            red[(r0 + 8) * RED_S + d + 1] = oacc[dt][3];
        }
    }
    __syncthreads();
    if (jc == 0) {
#pragma unroll
        for (int dt = 0; dt < 8; dt++) {
            int d = dt * 8 + c2;
            float2 lo = make_float2(oacc[dt][0] + red[r0 * RED_S + d],
                                    oacc[dt][1] + red[r0 * RED_S + d + 1]);
            float2 hi = make_float2(oacc[dt][2] + red[(r0 + 8) * RED_S + d],
                                    oacc[dt][3] + red[(r0 + 8) * RED_S + d + 1]);
            *(float2*)&dst[(size_t)(n0 + r0) * DIM + d]     = lo;
            *(float2*)&dst[(size_t)(n0 + r0 + 8) * DIM + d] = hi;
        }
    }
}

// ---------------------------------------------------------------------------
// Combine: Out += partial (band half 1)
// ---------------------------------------------------------------------------
__global__ __launch_bounds__(256) void combine_kernel(float* __restrict__ Out)
{
    int i = blockIdx.x * 256 + threadIdx.x;
    float4 a = ((float4*)Out)[i];
    float4 q = ((const float4*)g_P)[i];
    a.x += q.x; a.y += q.y; a.z += q.z; a.w += q.w;
    ((float4*)Out)[i] = a;
}

// ---------------------------------------------------------------------------
extern "C" void kernel_launch(void* const* d_in, const int* in_sizes, int n_in,
                              void* d_out, int out_size)
{
    const float* X  = (const float*)d_in[0];
    const float* Wq = (const float*)d_in[1];
    const float* Wk = (const float*)d_in[2];
    const float* Wv = (const float*)d_in[3];
    float* Out = (float*)d_out;

    cudaFuncSetAttribute(qkv_mma, cudaFuncAttributeMaxDynamicSharedMemorySize,
                         QKV_SMEM);
    cudaFuncSetAttribute(attn_mma, cudaFuncAttributeMaxDynamicSharedMemorySize,
                         ATTN_SMEM);

    prep_w<<<192 * HID / 256, 256>>>(Wq, Wk, Wv);
    prep_coef<<<LSEQ * 32 / 256, 256>>>();
    qkv_mma<<<NTOK / 64, 256, QKV_SMEM>>>(X);
    attn_mma<<<2 * BATCH * (LSEQ / 64), 256, ATTN_SMEM>>>(Out);
    combine_kernel<<<NTOK * DIM / 4 / 256, 256>>>(Out);
}

// round 9
// speedup vs baseline: 4.5116x; 1.0076x over previous
#include <cuda_runtime.h>
#include <cuda_bf16.h>
#include <stdint.h>

#define BATCH 2
#define LSEQ  4096
#define HID   1024
#define DIM   64
#define NTOK  (BATCH * LSEQ)
#define LOG2GAMMA (-0.04580368961f)   /* log2(0.96875) */

// ---------------------------------------------------------------------------
// Device globals
// ---------------------------------------------------------------------------
__device__ __nv_bfloat16 g_Qh[NTOK * DIM];
__device__ __nv_bfloat16 g_Ql[NTOK * DIM];
__device__ __nv_bfloat16 g_Kh[NTOK * DIM];
__device__ __nv_bfloat16 g_Kl[NTOK * DIM];
__device__ __nv_bfloat16 g_Vth[NTOK * DIM];       // per-64-tile transposed [t][d][tok]
__device__ __nv_bfloat16 g_Vtl[NTOK * DIM];
__device__ float g_P[NTOK * DIM];                 // partial O from band half 1
__device__ __nv_bfloat16 g_Wh[192 * HID];         // W^T concat [Q|K|V], hi part
__device__ __nv_bfloat16 g_Wl[192 * HID];         // lo part
__device__ float4 g_CO[LSEQ * 32];                // xPos coefs (cq,sq,ck,sk)

// ---------------------------------------------------------------------------
// Tensor-core helpers (sm_80+ portable: ldmatrix + mma.sync bf16 + cp.async)
// ---------------------------------------------------------------------------
__device__ __forceinline__ uint32_t smem_u32(const void* p) {
    uint32_t a;
    asm("{ .reg .u64 t; cvta.to.shared.u64 t, %1; cvt.u32.u64 %0, t; }"
        : "=r"(a) : "l"(p));
    return a;
}
__device__ __forceinline__ void ldsm4(uint32_t* r, uint32_t addr) {
    asm volatile("ldmatrix.sync.aligned.m8n8.x4.shared.b16 {%0,%1,%2,%3}, [%4];"
                 : "=r"(r[0]), "=r"(r[1]), "=r"(r[2]), "=r"(r[3]) : "r"(addr));
}
__device__ __forceinline__ void mma_bf16(float* d, const uint32_t* a,
                                         uint32_t b0, uint32_t b1) {
    asm volatile(
        "mma.sync.aligned.m16n8k16.row.col.f32.bf16.bf16.f32 "
        "{%0,%1,%2,%3},{%4,%5,%6,%7},{%8,%9},{%0,%1,%2,%3};"
        : "+f"(d[0]), "+f"(d[1]), "+f"(d[2]), "+f"(d[3])
        : "r"(a[0]), "r"(a[1]), "r"(a[2]), "r"(a[3]), "r"(b0), "r"(b1));
}
__device__ __forceinline__ uint32_t pack2(__nv_bfloat16 a, __nv_bfloat16 b) {
    __nv_bfloat162 p = __halves2bfloat162(a, b);
    return *(uint32_t*)&p;
}
__device__ __forceinline__ void cpasync16(uint32_t dst, const void* src) {
    asm volatile("cp.async.cg.shared.global [%0], [%1], 16;"
                 :: "r"(dst), "l"(src));
}
__device__ __forceinline__ void cp_commit() {
    asm volatile("cp.async.commit_group;" ::: "memory");
}
template <int N>
__device__ __forceinline__ void cp_wait() {
    asm volatile("cp.async.wait_group %0;" :: "n"(N) : "memory");
}

// ---------------------------------------------------------------------------
// Prep: W^T concat (192 x 1024) split into bf16 hi/lo
// ---------------------------------------------------------------------------
__global__ __launch_bounds__(256) void prep_w(
    const float* __restrict__ Wq, const float* __restrict__ Wk,
    const float* __restrict__ Wv)
{
    int idx = blockIdx.x * 256 + threadIdx.x;
    int n = idx >> 10;
    int k = idx & 1023;
    const float* W = (n < 64) ? Wq : ((n < 128) ? Wk : Wv);
    float v = W[k * DIM + (n & 63)];
    __nv_bfloat16 h = __float2bfloat16(v);
    __nv_bfloat16 l = __float2bfloat16(v - __bfloat162float(h));
    g_Wh[n * HID + k] = h;
    g_Wl[n * HID + k] = l;
}

// ---------------------------------------------------------------------------
// Prep: xPos coefficient table [l][pair i] -> (cq, sq, ck, sk)
// ---------------------------------------------------------------------------
__global__ __launch_bounds__(256) void prep_coef()
{
    int idx = blockIdx.x * 256 + threadIdx.x;
    int l = idx >> 5;
    int i = idx & 31;
    float fl = (float)l;
    float inv_freq = powf(10000.0f, -(float)i * (1.0f / 32.0f));
    float sn, cs;
    sincosf(fl * inv_freq, &sn, &cs);
    float sv = ((float)(2 * i) + 25.6f) / 89.6f;
    float scq = powf(sv, fl * (1.0f / 512.0f));
    g_CO[idx] = make_float4(cs * scq, sn * scq, cs / scq, sn / scq);
}

// ---------------------------------------------------------------------------
// QKV projection via mma.sync bf16 3-term split, software pipelined:
//   W hi/lo tiles: cp.async double-buffered (already bf16 in gmem)
//   X tile: LDG register prefetch of next chunk + convert-to-smem after compute
// Block 64 rows x 192 cols, 8 warps, warp tile 32 x 48; K chunks of 64.
// ---------------------------------------------------------------------------
#define XS    72
#define OXH   0
#define OXL   (OXH + 64 * XS * 2)
#define OW0   (OXL + 64 * XS * 2)                 /* W buffer 0: hi then lo */
#define OW1   (OW0 + 2 * 192 * XS * 2)            /* W buffer 1 */
#define OWLO  (192 * XS * 2)                      /* lo offset inside a W buffer */
#define QKV_SMEM (OW1 + 2 * 192 * XS * 2)         /* 129024 */

__global__ __launch_bounds__(256, 1) void qkv_mma(const float* __restrict__ X)
{
    extern __shared__ char smem[];
    const uint32_t sb = smem_u32(smem);
    const int tid  = threadIdx.x;
    const int lane = tid & 31;
    const int wid  = tid >> 5;
    const int mr   = (wid >> 2) * 32;
    const int nc   = (wid & 3) * 48;
    const int row0 = blockIdx.x * 64;

    // thread's X-load geometry: 4 float4 per chunk (64x64 fp32 tile)
    const int xr = tid >> 2;              // 0..63
    const int xc = (tid & 3) << 2;        // 0,4,8,12 (then +16 per it)

    // thread's W-copy geometry: 6 chunks of 16B per matrix (1536 total)
    const int wn0 = tid >> 3;             // 0..31 (row step 32)
    const int wc8 = (tid & 7) << 3;       // 0..56

    float acc[2][6][4];
#pragma unroll
    for (int a = 0; a < 2; a++)
#pragma unroll
        for (int b = 0; b < 6; b++)
#pragma unroll
            for (int c = 0; c < 4; c++) acc[a][b][c] = 0.f;

    // ---- prologue: W chunk 0 via cp.async; X chunk 0 via LDG+convert ----
    {
        const int kc = 0;
        uint32_t wb = sb + OW0;
#pragma unroll
        for (int it = 0; it < 6; it++) {
            int n = wn0 + it * 32;
            uint32_t off = (uint32_t)(n * XS + wc8) * 2;
            cpasync16(wb + off,        &g_Wh[n * HID + kc + wc8]);
            cpasync16(wb + OWLO + off, &g_Wl[n * HID + kc + wc8]);
        }
        cp_commit();
#pragma unroll
        for (int it = 0; it < 4; it++) {
            int c = xc + it * 16;
            float4 x = *(const float4*)&X[(size_t)(row0 + xr) * HID + kc + c];
            __nv_bfloat16 hx = __float2bfloat16(x.x);
            __nv_bfloat16 hy = __float2bfloat16(x.y);
            __nv_bfloat16 hz = __float2bfloat16(x.z);
            __nv_bfloat16 hw = __float2bfloat16(x.w);
            uint32_t off = (uint32_t)(xr * XS + c) * 2;
            *(uint2*)(smem + OXH + off) = make_uint2(pack2(hx, hy), pack2(hz, hw));
            *(uint2*)(smem + OXL + off) = make_uint2(
                pack2(__float2bfloat16(x.x - __bfloat162float(hx)),
                      __float2bfloat16(x.y - __bfloat162float(hy))),
                pack2(__float2bfloat16(x.z - __bfloat162float(hz)),
                      __float2bfloat16(x.w - __bfloat162float(hw))));
        }
    }

    for (int ch = 0; ch < 16; ch++) {
        const uint32_t wb = sb + ((ch & 1) ? OW1 : OW0);
        float4 xpre[4];
        if (ch < 15) {
            const int kcn = (ch + 1) * 64;
            // prefetch next W chunk into other buffer
            uint32_t wbn = sb + ((ch & 1) ? OW0 : OW1);
#pragma unroll
            for (int it = 0; it < 6; it++) {
                int n = wn0 + it * 32;
                uint32_t off = (uint32_t)(n * XS + wc8) * 2;
                cpasync16(wbn + off,        &g_Wh[n * HID + kcn + wc8]);
                cpasync16(wbn + OWLO + off, &g_Wl[n * HID + kcn + wc8]);
            }
            cp_commit();
            // prefetch next X chunk into registers
#pragma unroll
            for (int it = 0; it < 4; it++)
                xpre[it] = *(const float4*)&X[(size_t)(row0 + xr) * HID + kcn + xc + it * 16];
            cp_wait<1>();
        } else {
            cp_wait<0>();
        }
        __syncthreads();

        // ---- compute chunk ch ----
#pragma unroll
        for (int ks = 0; ks < 4; ks++) {
            const int lrow = lane & 15;
            const int lcol = ks * 16 + ((lane >> 4) << 3);
            uint32_t ah[2][4], al[2][4], bh[3][4], bl[3][4];
#pragma unroll
            for (int am = 0; am < 2; am++) {
                uint32_t off = (uint32_t)((mr + am * 16 + lrow) * XS + lcol) * 2;
                ldsm4(ah[am], sb + OXH + off);
                ldsm4(al[am], sb + OXL + off);
            }
#pragma unroll
            for (int nf = 0; nf < 3; nf++) {
                uint32_t off = (uint32_t)((nc + nf * 16 + lrow) * XS + lcol) * 2;
                ldsm4(bh[nf], wb + off);
                ldsm4(bl[nf], wb + OWLO + off);
            }
#pragma unroll
            for (int am = 0; am < 2; am++)
#pragma unroll
                for (int nf = 0; nf < 3; nf++) {
                    mma_bf16(acc[am][nf * 2],     ah[am], bh[nf][0], bh[nf][2]);
                    mma_bf16(acc[am][nf * 2],     ah[am], bl[nf][0], bl[nf][2]);
                    mma_bf16(acc[am][nf * 2],     al[am], bh[nf][0], bh[nf][2]);
                    mma_bf16(acc[am][nf * 2 + 1], ah[am], bh[nf][1], bh[nf][3]);
                    mma_bf16(acc[am][nf * 2 + 1], ah[am], bl[nf][1], bl[nf][3]);
                    mma_bf16(acc[am][nf * 2 + 1], al[am], bh[nf][1], bh[nf][3]);
                }
        }
        __syncthreads();

        // ---- convert prefetched X regs -> smem for chunk ch+1 ----
        if (ch < 15) {
#pragma unroll
            for (int it = 0; it < 4; it++) {
                int c = xc + it * 16;
                float4 x = xpre[it];
                __nv_bfloat16 hx = __float2bfloat16(x.x);
                __nv_bfloat16 hy = __float2bfloat16(x.y);
                __nv_bfloat16 hz = __float2bfloat16(x.z);
                __nv_bfloat16 hw = __float2bfloat16(x.w);
                uint32_t off = (uint32_t)(xr * XS + c) * 2;
                *(uint2*)(smem + OXH + off) = make_uint2(pack2(hx, hy), pack2(hz, hw));
                *(uint2*)(smem + OXL + off) = make_uint2(
                    pack2(__float2bfloat16(x.x - __bfloat162float(hx)),
                          __float2bfloat16(x.y - __bfloat162float(hy))),
                    pack2(__float2bfloat16(x.z - __bfloat162float(hz)),
                          __float2bfloat16(x.w - __bfloat162float(hw))));
            }
        }
    }

    // --- Epilogue ---
    const int r4 = lane >> 2;
    const int c2 = (lane & 3) * 2;
#pragma unroll
    for (int am = 0; am < 2; am++) {
#pragma unroll
        for (int h2 = 0; h2 < 2; h2++) {
            int g = row0 + mr + am * 16 + h2 * 8 + r4;
            int l = g & (LSEQ - 1);
#pragma unroll
            for (int nf = 0; nf < 6; nf++) {
                int col0 = nc + nf * 8;
                int mat  = col0 >> 6;
                int lcol = (col0 & 63) + c2;
                float v0 = acc[am][nf][h2 * 2 + 0];
                float v1 = acc[am][nf][h2 * 2 + 1];
                if (mat == 0) {
                    float4 co = g_CO[l * 32 + (lcol >> 1)];
                    float o0 = v0 * co.x - v1 * co.y;
                    float o1 = v1 * co.x + v0 * co.y;
                    __nv_bfloat16 h0 = __float2bfloat16(o0);
                    __nv_bfloat16 h1 = __float2bfloat16(o1);
                    *(uint32_t*)&g_Qh[g * DIM + lcol] = pack2(h0, h1);
                    *(uint32_t*)&g_Ql[g * DIM + lcol] =
                        pack2(__float2bfloat16(o0 - __bfloat162float(h0)),
                              __float2bfloat16(o1 - __bfloat162float(h1)));
                } else if (mat == 1) {
                    float4 co = g_CO[l * 32 + (lcol >> 1)];
                    float o0 = v0 * co.z - v1 * co.w;
                    float o1 = v1 * co.z + v0 * co.w;
                    __nv_bfloat16 h0 = __float2bfloat16(o0);
                    __nv_bfloat16 h1 = __float2bfloat16(o1);
                    *(uint32_t*)&g_Kh[g * DIM + lcol] = pack2(h0, h1);
                    *(uint32_t*)&g_Kl[g * DIM + lcol] =
                        pack2(__float2bfloat16(o0 - __bfloat162float(h0)),
                              __float2bfloat16(o1 - __bfloat162float(h1)));
                } else {
                    int t = g >> 6, tok = g & 63;
                    __nv_bfloat16 h0 = __float2bfloat16(v0);
                    __nv_bfloat16 h1 = __float2bfloat16(v1);
                    g_Vth[t * 4096 + lcol * 64 + tok]       = h0;
                    g_Vth[t * 4096 + (lcol + 1) * 64 + tok] = h1;
                    g_Vtl[t * 4096 + lcol * 64 + tok] =
                        __float2bfloat16(v0 - __bfloat162float(h0));
                    g_Vtl[t * 4096 + (lcol + 1) * 64 + tok] =
                        __float2bfloat16(v1 - __bfloat162float(h1));
                }
            }
        }
    }
}

// ---------------------------------------------------------------------------
// Banded decay attention on tensor cores (unchanged from R8).
// Band = 8 tiles, split 4+4 over p=0 (-> Out) / p=1 (-> g_P). Grid 256.
// ---------------------------------------------------------------------------
#define AS     72
#define OQH_A  0
#define OQL_A  (OQH_A + 64 * AS * 2)
#define OKH_A  (OQL_A + 64 * AS * 2)
#define OKL_A  (OKH_A + 64 * AS * 2)
#define OVH_A  (OKL_A + 64 * AS * 2)
#define OVL_A  (OVH_A + 64 * AS * 2)
#define ATTN_SMEM (OVL_A + 64 * AS * 2)   /* 55296 */
#define RED_S  68

__global__ __launch_bounds__(256) void attn_mma(float* __restrict__ Out)
{
    extern __shared__ char sm[];
    const uint32_t sb = smem_u32(sm);
    const int tid  = threadIdx.x;
    const int lane = tid & 31;
    const int wid  = tid >> 5;
    const int rg   = wid & 3;
    const int jc   = wid >> 2;
    const int p    = blockIdx.x >> 7;
    const int b    = (blockIdx.x >> 6) & 1;
    const int qt   = blockIdx.x & 63;
    const int n0   = b * LSEQ + qt * 64;

    float* __restrict__ dst = p ? g_P : Out;

    int kt0, kt1;
    if (p == 0) { kt0 = qt - 3; if (kt0 < 0) kt0 = 0; kt1 = qt; }
    else        { kt0 = qt - 7; if (kt0 < 0) kt0 = 0; kt1 = qt - 4; }

    if (kt1 < kt0) {
        float4 z = make_float4(0.f, 0.f, 0.f, 0.f);
        for (int t = tid; t < 64 * DIM / 4; t += 256)
            ((float4*)&dst[(size_t)n0 * DIM])[t] = z;
        return;
    }

#pragma unroll
    for (int it = 0; it < 2; it++) {
        int s = it * 256 + tid;
        int r = s >> 3, c8 = (s & 7) << 3;
        uint32_t off = (uint32_t)(r * AS + c8) * 2;
        *(uint4*)(sm + OQH_A + off) = *(const uint4*)&g_Qh[(size_t)(n0 + r) * DIM + c8];
        *(uint4*)(sm + OQL_A + off) = *(const uint4*)&g_Ql[(size_t)(n0 + r) * DIM + c8];
    }

    float oacc[8][4];
#pragma unroll
    for (int d = 0; d < 8; d++)
#pragma unroll
        for (int c = 0; c < 4; c++) oacc[d][c] = 0.f;

    const int r0 = rg * 16 + (lane >> 2);
    const float gi0 = exp2f((float)r0 * LOG2GAMMA);
    const float gi1 = exp2f((float)(r0 + 8) * LOG2GAMMA);
    float gj[4][2];
#pragma unroll
    for (int jt = 0; jt < 4; jt++) {
        int j = jc * 32 + jt * 8 + ((lane & 3) << 1);
        gj[jt][0] = exp2f(-(float)j * LOG2GAMMA);
        gj[jt][1] = exp2f(-(float)(j + 1) * LOG2GAMMA);
    }

    const int lrow = lane & 15;
    const int lcg  = (lane >> 4) << 3;

    for (int kt = kt0; kt <= kt1; kt++) {
        const int m0 = b * LSEQ + kt * 64;
        const int tile = m0 >> 6;
        __syncthreads();
#pragma unroll
        for (int it = 0; it < 2; it++) {
            int s = it * 256 + tid;
            int r = s >> 3, c8 = (s & 7) << 3;
            uint32_t off = (uint32_t)(r * AS + c8) * 2;
            *(uint4*)(sm + OKH_A + off) = *(const uint4*)&g_Kh[(size_t)(m0 + r) * DIM + c8];
            *(uint4*)(sm + OKL_A + off) = *(const uint4*)&g_Kl[(size_t)(m0 + r) * DIM + c8];
            *(uint4*)(sm + OVH_A + off) = *(const uint4*)&g_Vth[(size_t)tile * 4096 + r * 64 + c8];
            *(uint4*)(sm + OVL_A + off) = *(const uint4*)&g_Vtl[(size_t)tile * 4096 + r * 64 + c8];
        }
        __syncthreads();

        float sfrag[4][4];
#pragma unroll
        for (int jt = 0; jt < 4; jt++)
#pragma unroll
            for (int c = 0; c < 4; c++) sfrag[jt][c] = 0.f;

#pragma unroll
        for (int ks = 0; ks < 4; ks++) {
            uint32_t aoff = (uint32_t)((rg * 16 + lrow) * AS + ks * 16 + lcg) * 2;
            uint32_t ah[4], al[4];
            ldsm4(ah, sb + OQH_A + aoff);
            ldsm4(al, sb + OQL_A + aoff);
            uint32_t bh[2][4], bl[2][4];
#pragma unroll
            for (int jg = 0; jg < 2; jg++) {
                uint32_t boff = (uint32_t)((jc * 32 + jg * 16 + lrow) * AS + ks * 16 + lcg) * 2;
                ldsm4(bh[jg], sb + OKH_A + boff);
                ldsm4(bl[jg], sb + OKL_A + boff);
            }
#pragma unroll
            for (int jt = 0; jt < 4; jt++) {
                int jg = jt >> 1, sel = jt & 1;
                uint32_t b0h = bh[jg][sel], b1h = bh[jg][sel + 2];
                uint32_t b0l = bl[jg][sel], b1l = bl[jg][sel + 2];
                mma_bf16(sfrag[jt], ah, b0h, b1h);
                mma_bf16(sfrag[jt], ah, b0l, b1l);
                mma_bf16(sfrag[jt], al, b0h, b1h);
            }
        }

        const float basekt = exp2f((float)((qt - kt) * 64) * LOG2GAMMA);
        uint32_t shh[2][4], sll[2][4];
#pragma unroll
        for (int jt = 0; jt < 4; jt++) {
            float w0 = basekt * gj[jt][0];
            float w1 = basekt * gj[jt][1];
            float v0 = sfrag[jt][0] * gi0 * w0;
            float v1 = sfrag[jt][1] * gi0 * w1;
            float v2 = sfrag[jt][2] * gi1 * w0;
            float v3 = sfrag[jt][3] * gi1 * w1;
            if (kt == qt) {
                int j0 = jc * 32 + jt * 8 + ((lane & 3) << 1);
                if (r0 < j0)         v0 = 0.f;
                if (r0 < j0 + 1)     v1 = 0.f;
                if (r0 + 8 < j0)     v2 = 0.f;
                if (r0 + 8 < j0 + 1) v3 = 0.f;
            }
            __nv_bfloat16 h0 = __float2bfloat16(v0);
            __nv_bfloat16 h1 = __float2bfloat16(v1);
            __nv_bfloat16 h2 = __float2bfloat16(v2);
            __nv_bfloat16 h3 = __float2bfloat16(v3);
            int ks2 = jt >> 1, odd = jt & 1;
            shh[ks2][odd * 2 + 0] = pack2(h0, h1);
            shh[ks2][odd * 2 + 1] = pack2(h2, h3);
            sll[ks2][odd * 2 + 0] =
                pack2(__float2bfloat16(v0 - __bfloat162float(h0)),
                      __float2bfloat16(v1 - __bfloat162float(h1)));
            sll[ks2][odd * 2 + 1] =
                pack2(__float2bfloat16(v2 - __bfloat162float(h2)),
                      __float2bfloat16(v3 - __bfloat162float(h3)));
        }

#pragma unroll
        for (int ks2 = 0; ks2 < 2; ks2++) {
            uint32_t vbh[4][4], vbl[4][4];
#pragma unroll
            for (int dg = 0; dg < 4; dg++) {
                uint32_t voff = (uint32_t)((dg * 16 + lrow) * AS + jc * 32 + ks2 * 16 + lcg) * 2;
                ldsm4(vbh[dg], sb + OVH_A + voff);
                ldsm4(vbl[dg], sb + OVL_A + voff);
            }
#pragma unroll
            for (int dt = 0; dt < 8; dt++) {
                int dg = dt >> 1, sel = dt & 1;
                uint32_t b0h = vbh[dg][sel], b1h = vbh[dg][sel + 2];
                uint32_t b0l = vbl[dg][sel], b1l = vbl[dg][sel + 2];
                mma_bf16(oacc[dt], shh[ks2], b0h, b1h);
                mma_bf16(oacc[dt], sll[ks2], b0h, b1h);
                mma_bf16(oacc[dt], shh[ks2], b0l, b1l);
            }
        }
    }

    __syncthreads();
    float* red = (float*)sm;
    const int c2 = (lane & 3) << 1;
    if (jc == 1) {
#pragma unroll
        for (int dt = 0; dt < 8; dt++) {
            int d = dt * 8 + c2;
            red[r0 * RED_S + d]           = oacc[dt][0];
            red[r0 * RED_S + d + 1]       = oacc[dt][1];
            red[(r0 + 8) * RED_S + d]     = oacc[dt][2];
            red[(r0 + 8) * RED_S + d + 1] = oacc[dt][3];
        }
    }
    __syncthreads();
    if (jc == 0) {
#pragma unroll
        for (int dt = 0; dt < 8; dt++) {
            int d = dt * 8 + c2;
            float2 lo = make_float2(oacc[dt][0] + red[r0 * RED_S + d],
                                    oacc[dt][1] + red[r0 * RED_S + d + 1]);
            float2 hi = make_float2(oacc[dt][2] + red[(r0 + 8) * RED_S + d],
                                    oacc[dt][3] + red[(r0 + 8) * RED_S + d + 1]);
            *(float2*)&dst[(size_t)(n0 + r0) * DIM + d]     = lo;
            *(float2*)&dst[(size_t)(n0 + r0 + 8) * DIM + d] = hi;
        }
    }
}

// ---------------------------------------------------------------------------
// Combine: Out += partial (band half 1)
// ---------------------------------------------------------------------------
__global__ __launch_bounds__(256) void combine_kernel(float* __restrict__ Out)
{
    int i = blockIdx.x * 256 + threadIdx.x;
    float4 a = ((float4*)Out)[i];
    float4 q = ((const float4*)g_P)[i];
    a.x += q.x; a.y += q.y; a.z += q.z; a.w += q.w;
    ((float4*)Out)[i] = a;
}

// ---------------------------------------------------------------------------
extern "C" void kernel_launch(void* const* d_in, const int* in_sizes, int n_in,
                              void* d_out, int out_size)
{
    const float* X  = (const float*)d_in[0];
    const float* Wq = (const float*)d_in[1];
    const float* Wk = (const float*)d_in[2];
    const float* Wv = (const float*)d_in[3];
    float* Out = (float*)d_out;

    cudaFuncSetAttribute(qkv_mma, cudaFuncAttributeMaxDynamicSharedMemorySize,
                         QKV_SMEM);
    cudaFuncSetAttribute(attn_mma, cudaFuncAttributeMaxDynamicSharedMemorySize,
                         ATTN_SMEM);

    prep_w<<<192 * HID / 256, 256>>>(Wq, Wk, Wv);
    prep_coef<<<LSEQ * 32 / 256, 256>>>();
    qkv_mma<<<NTOK / 64, 256, QKV_SMEM>>>(X);
    attn_mma<<<2 * BATCH * (LSEQ / 64), 256, ATTN_SMEM>>>(Out);
    combine_kernel<<<NTOK * DIM / 4 / 256, 256>>>(Out);
}

// round 10
// speedup vs baseline: 4.7690x; 1.0570x over previous
#include <cuda_runtime.h>
#include <cuda_bf16.h>
#include <stdint.h>

#define BATCH 2
#define LSEQ  4096
#define HID   1024
#define DIM   64
#define NTOK  (BATCH * LSEQ)
#define LOG2GAMMA (-0.04580368961f)   /* log2(0.96875) */

// ---------------------------------------------------------------------------
// Device globals
// ---------------------------------------------------------------------------
__device__ __nv_bfloat16 g_Qh[NTOK * DIM];
__device__ __nv_bfloat16 g_Ql[NTOK * DIM];
__device__ __nv_bfloat16 g_Kh[NTOK * DIM];
__device__ __nv_bfloat16 g_Kl[NTOK * DIM];
__device__ __nv_bfloat16 g_Vth[NTOK * DIM];       // per-64-tile transposed [t][d][tok]
__device__ __nv_bfloat16 g_Vtl[NTOK * DIM];
__device__ float g_P[NTOK * DIM];                 // partial O from band half 1
__device__ __nv_bfloat16 g_Wh[192 * HID];         // W^T concat [Q|K|V], hi part
__device__ __nv_bfloat16 g_Wl[192 * HID];         // lo part
__device__ float4 g_CO[LSEQ * 32];                // xPos coefs (cq,sq,ck,sk)

// ---------------------------------------------------------------------------
// Tensor-core helpers (sm_80+ portable: ldmatrix + mma.sync bf16 + cp.async)
// ---------------------------------------------------------------------------
__device__ __forceinline__ uint32_t smem_u32(const void* p) {
    uint32_t a;
    asm("{ .reg .u64 t; cvta.to.shared.u64 t, %1; cvt.u32.u64 %0, t; }"
        : "=r"(a) : "l"(p));
    return a;
}
__device__ __forceinline__ void ldsm4(uint32_t* r, uint32_t addr) {
    asm volatile("ldmatrix.sync.aligned.m8n8.x4.shared.b16 {%0,%1,%2,%3}, [%4];"
                 : "=r"(r[0]), "=r"(r[1]), "=r"(r[2]), "=r"(r[3]) : "r"(addr));
}
__device__ __forceinline__ void mma_bf16(float* d, const uint32_t* a,
                                         uint32_t b0, uint32_t b1) {
    asm volatile(
        "mma.sync.aligned.m16n8k16.row.col.f32.bf16.bf16.f32 "
        "{%0,%1,%2,%3},{%4,%5,%6,%7},{%8,%9},{%0,%1,%2,%3};"
        : "+f"(d[0]), "+f"(d[1]), "+f"(d[2]), "+f"(d[3])
        : "r"(a[0]), "r"(a[1]), "r"(a[2]), "r"(a[3]), "r"(b0), "r"(b1));
}
__device__ __forceinline__ uint32_t pack2(__nv_bfloat16 a, __nv_bfloat16 b) {
    __nv_bfloat162 p = __halves2bfloat162(a, b);
    return *(uint32_t*)&p;
}
__device__ __forceinline__ void cpasync16(uint32_t dst, const void* src) {
    asm volatile("cp.async.cg.shared.global [%0], [%1], 16;"
                 :: "r"(dst), "l"(src));
}
__device__ __forceinline__ void cp_commit() {
    asm volatile("cp.async.commit_group;" ::: "memory");
}
template <int N>
__device__ __forceinline__ void cp_wait() {
    asm volatile("cp.async.wait_group %0;" :: "n"(N) : "memory");
}

// ---------------------------------------------------------------------------
// Prep: W^T concat (192 x 1024) split into bf16 hi/lo
// ---------------------------------------------------------------------------
__global__ __launch_bounds__(256) void prep_w(
    const float* __restrict__ Wq, const float* __restrict__ Wk,
    const float* __restrict__ Wv)
{
    int idx = blockIdx.x * 256 + threadIdx.x;
    int n = idx >> 10;
    int k = idx & 1023;
    const float* W = (n < 64) ? Wq : ((n < 128) ? Wk : Wv);
    float v = W[k * DIM + (n & 63)];
    __nv_bfloat16 h = __float2bfloat16(v);
    __nv_bfloat16 l = __float2bfloat16(v - __bfloat162float(h));
    g_Wh[n * HID + k] = h;
    g_Wl[n * HID + k] = l;
}

// ---------------------------------------------------------------------------
// Prep: xPos coefficient table [l][pair i] -> (cq, sq, ck, sk)
// powf replaced with log2/exp2 (fewer MUFU ops); sincosf kept for range safety.
// ---------------------------------------------------------------------------
__global__ __launch_bounds__(256) void prep_coef()
{
    int idx = blockIdx.x * 256 + threadIdx.x;
    int l = idx >> 5;
    int i = idx & 31;
    float fl = (float)l;
    // inv_freq = 10000^(-i/32) = exp2(-i * log2(10000)/32)
    float inv_freq = exp2f(-(float)i * (13.287712379549449f / 32.0f));
    float sn, cs;
    sincosf(fl * inv_freq, &sn, &cs);
    float sv = ((float)(2 * i) + 25.6f) / 89.6f;
    // sv^(l/512) = exp2(l * log2(sv)/512)
    float scq = exp2f(fl * (log2f(sv) * (1.0f / 512.0f)));
    g_CO[idx] = make_float4(cs * scq, sn * scq, cs / scq, sn / scq);
}

// ---------------------------------------------------------------------------
// QKV projection via mma.sync bf16 3-term split, 512 threads (16 warps, 4x4
// warp grid, warp tile 16x48) for 4 warps/SMSP issue density.
// W hi/lo double-buffered cp.async; X register-prefetched + converted.
// ---------------------------------------------------------------------------
#define XS    72
#define OXH   0
#define OXL   (OXH + 64 * XS * 2)
#define OW0   (OXL + 64 * XS * 2)
#define OW1   (OW0 + 2 * 192 * XS * 2)
#define OWLO  (192 * XS * 2)
#define QKV_SMEM (OW1 + 2 * 192 * XS * 2)         /* 129024 */

__global__ __launch_bounds__(512, 1) void qkv_mma(const float* __restrict__ X)
{
    extern __shared__ char smem[];
    const uint32_t sb = smem_u32(smem);
    const int tid  = threadIdx.x;
    const int lane = tid & 31;
    const int wid  = tid >> 5;          // 0..15
    const int mr   = (wid >> 2) * 16;   // 4 row groups of 16
    const int nc   = (wid & 3) * 48;    // 4 col groups of 48
    const int row0 = blockIdx.x * 64;

    // X-load geometry: 8 threads/row, 2 float4 each
    const int xr = tid >> 3;            // 0..63
    const int xc = (tid & 7) << 2;      // float col 0..28 (then +32)

    // W-copy geometry: 3 row-steps of 64, 16B per step per matrix
    const int wn0 = tid >> 3;           // 0..63
    const int wc8 = (tid & 7) << 3;     // 0..56

    float acc[6][4];
#pragma unroll
    for (int b = 0; b < 6; b++)
#pragma unroll
        for (int c = 0; c < 4; c++) acc[b][c] = 0.f;

    // ---- prologue ----
    {
        uint32_t wb = sb + OW0;
#pragma unroll
        for (int it = 0; it < 3; it++) {
            int n = wn0 + it * 64;
            uint32_t off = (uint32_t)(n * XS + wc8) * 2;
            cpasync16(wb + off,        &g_Wh[n * HID + wc8]);
            cpasync16(wb + OWLO + off, &g_Wl[n * HID + wc8]);
        }
        cp_commit();
#pragma unroll
        for (int it = 0; it < 2; it++) {
            int c = xc + it * 32;
            float4 x = *(const float4*)&X[(size_t)(row0 + xr) * HID + c];
            __nv_bfloat16 hx = __float2bfloat16(x.x);
            __nv_bfloat16 hy = __float2bfloat16(x.y);
            __nv_bfloat16 hz = __float2bfloat16(x.z);
            __nv_bfloat16 hw = __float2bfloat16(x.w);
            uint32_t off = (uint32_t)(xr * XS + c) * 2;
            *(uint2*)(smem + OXH + off) = make_uint2(pack2(hx, hy), pack2(hz, hw));
            *(uint2*)(smem + OXL + off) = make_uint2(
                pack2(__float2bfloat16(x.x - __bfloat162float(hx)),
                      __float2bfloat16(x.y - __bfloat162float(hy))),
                pack2(__float2bfloat16(x.z - __bfloat162float(hz)),
                      __float2bfloat16(x.w - __bfloat162float(hw))));
        }
    }

    for (int ch = 0; ch < 16; ch++) {
        const uint32_t wb = sb + ((ch & 1) ? OW1 : OW0);
        float4 xpre[2];
        if (ch < 15) {
            const int kcn = (ch + 1) * 64;
            uint32_t wbn = sb + ((ch & 1) ? OW0 : OW1);
#pragma unroll
            for (int it = 0; it < 3; it++) {
                int n = wn0 + it * 64;
                uint32_t off = (uint32_t)(n * XS + wc8) * 2;
                cpasync16(wbn + off,        &g_Wh[n * HID + kcn + wc8]);
                cpasync16(wbn + OWLO + off, &g_Wl[n * HID + kcn + wc8]);
            }
            cp_commit();
#pragma unroll
            for (int it = 0; it < 2; it++)
                xpre[it] = *(const float4*)&X[(size_t)(row0 + xr) * HID + kcn + xc + it * 32];
            cp_wait<1>();
        } else {
            cp_wait<0>();
        }
        __syncthreads();

        // ---- compute chunk ch ----
        const int lrow = lane & 15;
        const int lcg  = (lane >> 4) << 3;
#pragma unroll
        for (int ks = 0; ks < 4; ks++) {
            const int lcol = ks * 16 + lcg;
            uint32_t ah[4], al[4], bh[3][4], bl[3][4];
            {
                uint32_t off = (uint32_t)((mr + lrow) * XS + lcol) * 2;
                ldsm4(ah, sb + OXH + off);
                ldsm4(al, sb + OXL + off);
            }
#pragma unroll
            for (int nf = 0; nf < 3; nf++) {
                uint32_t off = (uint32_t)((nc + nf * 16 + lrow) * XS + lcol) * 2;
                ldsm4(bh[nf], wb + off);
                ldsm4(bl[nf], wb + OWLO + off);
            }
#pragma unroll
            for (int nf = 0; nf < 3; nf++) {
                mma_bf16(acc[nf * 2],     ah, bh[nf][0], bh[nf][2]);
                mma_bf16(acc[nf * 2],     ah, bl[nf][0], bl[nf][2]);
                mma_bf16(acc[nf * 2],     al, bh[nf][0], bh[nf][2]);
                mma_bf16(acc[nf * 2 + 1], ah, bh[nf][1], bh[nf][3]);
                mma_bf16(acc[nf * 2 + 1], ah, bl[nf][1], bl[nf][3]);
                mma_bf16(acc[nf * 2 + 1], al, bh[nf][1], bh[nf][3]);
            }
        }
        __syncthreads();

        if (ch < 15) {
#pragma unroll
            for (int it = 0; it < 2; it++) {
                int c = xc + it * 32;
                float4 x = xpre[it];
                __nv_bfloat16 hx = __float2bfloat16(x.x);
                __nv_bfloat16 hy = __float2bfloat16(x.y);
                __nv_bfloat16 hz = __float2bfloat16(x.z);
                __nv_bfloat16 hw = __float2bfloat16(x.w);
                uint32_t off = (uint32_t)(xr * XS + c) * 2;
                *(uint2*)(smem + OXH + off) = make_uint2(pack2(hx, hy), pack2(hz, hw));
                *(uint2*)(smem + OXL + off) = make_uint2(
                    pack2(__float2bfloat16(x.x - __bfloat162float(hx)),
                          __float2bfloat16(x.y - __bfloat162float(hy))),
                    pack2(__float2bfloat16(x.z - __bfloat162float(hz)),
                          __float2bfloat16(x.w - __bfloat162float(hw))));
            }
        }
    }

    // --- Epilogue: xPos + hi/lo split for Q/K; V transposed hi/lo ---
    const int r4 = lane >> 2;
    const int c2 = (lane & 3) * 2;
#pragma unroll
    for (int h2 = 0; h2 < 2; h2++) {
        int g = row0 + mr + h2 * 8 + r4;
        int l = g & (LSEQ - 1);
#pragma unroll
        for (int nf = 0; nf < 6; nf++) {
            int col0 = nc + nf * 8;
            int mat  = col0 >> 6;
            int lcol = (col0 & 63) + c2;
            float v0 = acc[nf][h2 * 2 + 0];
            float v1 = acc[nf][h2 * 2 + 1];
            if (mat == 0) {
                float4 co = g_CO[l * 32 + (lcol >> 1)];
                float o0 = v0 * co.x - v1 * co.y;
                float o1 = v1 * co.x + v0 * co.y;
                __nv_bfloat16 h0 = __float2bfloat16(o0);
                __nv_bfloat16 h1 = __float2bfloat16(o1);
                *(uint32_t*)&g_Qh[g * DIM + lcol] = pack2(h0, h1);
                *(uint32_t*)&g_Ql[g * DIM + lcol] =
                    pack2(__float2bfloat16(o0 - __bfloat162float(h0)),
                          __float2bfloat16(o1 - __bfloat162float(h1)));
            } else if (mat == 1) {
                float4 co = g_CO[l * 32 + (lcol >> 1)];
                float o0 = v0 * co.z - v1 * co.w;
                float o1 = v1 * co.z + v0 * co.w;
                __nv_bfloat16 h0 = __float2bfloat16(o0);
                __nv_bfloat16 h1 = __float2bfloat16(o1);
                *(uint32_t*)&g_Kh[g * DIM + lcol] = pack2(h0, h1);
                *(uint32_t*)&g_Kl[g * DIM + lcol] =
                    pack2(__float2bfloat16(o0 - __bfloat162float(h0)),
                          __float2bfloat16(o1 - __bfloat162float(h1)));
            } else {
                int t = g >> 6, tok = g & 63;
                __nv_bfloat16 h0 = __float2bfloat16(v0);
                __nv_bfloat16 h1 = __float2bfloat16(v1);
                g_Vth[t * 4096 + lcol * 64 + tok]       = h0;
                g_Vth[t * 4096 + (lcol + 1) * 64 + tok] = h1;
                g_Vtl[t * 4096 + lcol * 64 + tok] =
                    __float2bfloat16(v0 - __bfloat162float(h0));
                g_Vtl[t * 4096 + (lcol + 1) * 64 + tok] =
                    __float2bfloat16(v1 - __bfloat162float(h1));
            }
        }
    }
}

// ---------------------------------------------------------------------------
// Banded decay attention, precision-tiered:
//   p=0: kt in [qt-2, qt] (decay >= gamma^191) -> 3-term bf16, writes Out
//   p=1: kt in [qt-7, qt-3] (decay <= gamma^129) -> 1-term bf16, writes g_P
// Grid 256 blocks, 8 warps; warp (rg, jc) as in R8.
// ---------------------------------------------------------------------------
#define AS     72
#define OQH_A  0
#define OQL_A  (OQH_A + 64 * AS * 2)
#define OKH_A  (OQL_A + 64 * AS * 2)
#define OKL_A  (OKH_A + 64 * AS * 2)
#define OVH_A  (OKL_A + 64 * AS * 2)
#define OVL_A  (OVH_A + 64 * AS * 2)
#define ATTN_SMEM (OVL_A + 64 * AS * 2)   /* 55296 */
#define RED_S  68

__global__ __launch_bounds__(256) void attn_mma(float* __restrict__ Out)
{
    extern __shared__ char sm[];
    const uint32_t sb = smem_u32(sm);
    const int tid  = threadIdx.x;
    const int lane = tid & 31;
    const int wid  = tid >> 5;
    const int rg   = wid & 3;
    const int jc   = wid >> 2;
    const int p    = blockIdx.x >> 7;
    const int b    = (blockIdx.x >> 6) & 1;
    const int qt   = blockIdx.x & 63;
    const int n0   = b * LSEQ + qt * 64;
    const bool t3  = (p == 0);          // 3-term tier

    float* __restrict__ dst = p ? g_P : Out;

    int kt0, kt1;
    if (p == 0) { kt0 = qt - 2; if (kt0 < 0) kt0 = 0; kt1 = qt; }
    else        { kt0 = qt - 7; if (kt0 < 0) kt0 = 0; kt1 = qt - 3; }

    if (kt1 < kt0) {
        float4 z = make_float4(0.f, 0.f, 0.f, 0.f);
        for (int t = tid; t < 64 * DIM / 4; t += 256)
            ((float4*)&dst[(size_t)n0 * DIM])[t] = z;
        return;
    }

#pragma unroll
    for (int it = 0; it < 2; it++) {
        int s = it * 256 + tid;
        int r = s >> 3, c8 = (s & 7) << 3;
        uint32_t off = (uint32_t)(r * AS + c8) * 2;
        *(uint4*)(sm + OQH_A + off) = *(const uint4*)&g_Qh[(size_t)(n0 + r) * DIM + c8];
        if (t3)
            *(uint4*)(sm + OQL_A + off) = *(const uint4*)&g_Ql[(size_t)(n0 + r) * DIM + c8];
    }

    float oacc[8][4];
#pragma unroll
    for (int d = 0; d < 8; d++)
#pragma unroll
        for (int c = 0; c < 4; c++) oacc[d][c] = 0.f;

    const int r0 = rg * 16 + (lane >> 2);
    const float gi0 = exp2f((float)r0 * LOG2GAMMA);
    const float gi1 = exp2f((float)(r0 + 8) * LOG2GAMMA);
    float gj[4][2];
#pragma unroll
    for (int jt = 0; jt < 4; jt++) {
        int j = jc * 32 + jt * 8 + ((lane & 3) << 1);
        gj[jt][0] = exp2f(-(float)j * LOG2GAMMA);
        gj[jt][1] = exp2f(-(float)(j + 1) * LOG2GAMMA);
    }

    const int lrow = lane & 15;
    const int lcg  = (lane >> 4) << 3;

    for (int kt = kt0; kt <= kt1; kt++) {
        const int m0 = b * LSEQ + kt * 64;
        const int tile = m0 >> 6;
        __syncthreads();
#pragma unroll
        for (int it = 0; it < 2; it++) {
            int s = it * 256 + tid;
            int r = s >> 3, c8 = (s & 7) << 3;
            uint32_t off = (uint32_t)(r * AS + c8) * 2;
            *(uint4*)(sm + OKH_A + off) = *(const uint4*)&g_Kh[(size_t)(m0 + r) * DIM + c8];
            *(uint4*)(sm + OVH_A + off) = *(const uint4*)&g_Vth[(size_t)tile * 4096 + r * 64 + c8];
            if (t3) {
                *(uint4*)(sm + OKL_A + off) = *(const uint4*)&g_Kl[(size_t)(m0 + r) * DIM + c8];
                *(uint4*)(sm + OVL_A + off) = *(const uint4*)&g_Vtl[(size_t)tile * 4096 + r * 64 + c8];
            }
        }
        __syncthreads();

        // ---- S = Q K^T ----
        float sfrag[4][4];
#pragma unroll
        for (int jt = 0; jt < 4; jt++)
#pragma unroll
            for (int c = 0; c < 4; c++) sfrag[jt][c] = 0.f;

#pragma unroll
        for (int ks = 0; ks < 4; ks++) {
            uint32_t aoff = (uint32_t)((rg * 16 + lrow) * AS + ks * 16 + lcg) * 2;
            uint32_t ah[4], al[4];
            ldsm4(ah, sb + OQH_A + aoff);
            if (t3) ldsm4(al, sb + OQL_A + aoff);
            uint32_t bh[2][4], bl[2][4];
#pragma unroll
            for (int jg = 0; jg < 2; jg++) {
                uint32_t boff = (uint32_t)((jc * 32 + jg * 16 + lrow) * AS + ks * 16 + lcg) * 2;
                ldsm4(bh[jg], sb + OKH_A + boff);
                if (t3) ldsm4(bl[jg], sb + OKL_A + boff);
            }
#pragma unroll
            for (int jt = 0; jt < 4; jt++) {
                int jg = jt >> 1, sel = jt & 1;
                uint32_t b0h = bh[jg][sel], b1h = bh[jg][sel + 2];
                mma_bf16(sfrag[jt], ah, b0h, b1h);
                if (t3) {
                    mma_bf16(sfrag[jt], ah, bl[jg][sel], bl[jg][sel + 2]);
                    mma_bf16(sfrag[jt], al, b0h, b1h);
                }
            }
        }

        // ---- decay + mask + frag-direct hi/lo conversion ----
        const float basekt = exp2f((float)((qt - kt) * 64) * LOG2GAMMA);
        uint32_t shh[2][4], sll[2][4];
#pragma unroll
        for (int jt = 0; jt < 4; jt++) {
            float w0 = basekt * gj[jt][0];
            float w1 = basekt * gj[jt][1];
            float v0 = sfrag[jt][0] * gi0 * w0;
            float v1 = sfrag[jt][1] * gi0 * w1;
            float v2 = sfrag[jt][2] * gi1 * w0;
            float v3 = sfrag[jt][3] * gi1 * w1;
            if (kt == qt) {
                int j0 = jc * 32 + jt * 8 + ((lane & 3) << 1);
                if (r0 < j0)         v0 = 0.f;
                if (r0 < j0 + 1)     v1 = 0.f;
                if (r0 + 8 < j0)     v2 = 0.f;
                if (r0 + 8 < j0 + 1) v3 = 0.f;
            }
            __nv_bfloat16 h0 = __float2bfloat16(v0);
            __nv_bfloat16 h1 = __float2bfloat16(v1);
            __nv_bfloat16 h2 = __float2bfloat16(v2);
            __nv_bfloat16 h3 = __float2bfloat16(v3);
            int ks2 = jt >> 1, odd = jt & 1;
            shh[ks2][odd * 2 + 0] = pack2(h0, h1);
            shh[ks2][odd * 2 + 1] = pack2(h2, h3);
            if (t3) {
                sll[ks2][odd * 2 + 0] =
                    pack2(__float2bfloat16(v0 - __bfloat162float(h0)),
                          __float2bfloat16(v1 - __bfloat162float(h1)));
                sll[ks2][odd * 2 + 1] =
                    pack2(__float2bfloat16(v2 - __bfloat162float(h2)),
                          __float2bfloat16(v3 - __bfloat162float(h3)));
            }
        }

        // ---- O += S V ----
#pragma unroll
        for (int ks2 = 0; ks2 < 2; ks2++) {
            uint32_t vbh[4][4], vbl[4][4];
#pragma unroll
            for (int dg = 0; dg < 4; dg++) {
                uint32_t voff = (uint32_t)((dg * 16 + lrow) * AS + jc * 32 + ks2 * 16 + lcg) * 2;
                ldsm4(vbh[dg], sb + OVH_A + voff);
                if (t3) ldsm4(vbl[dg], sb + OVL_A + voff);
            }
#pragma unroll
            for (int dt = 0; dt < 8; dt++) {
                int dg = dt >> 1, sel = dt & 1;
                uint32_t b0h = vbh[dg][sel], b1h = vbh[dg][sel + 2];
                mma_bf16(oacc[dt], shh[ks2], b0h, b1h);
                if (t3) {
                    mma_bf16(oacc[dt], sll[ks2], b0h, b1h);
                    mma_bf16(oacc[dt], shh[ks2], vbl[dg][sel], vbl[dg][sel + 2]);
                }
            }
        }
    }

    // ---- pair reduction (w, w+4) over smem, then store ----
    __syncthreads();
    float* red = (float*)sm;
    const int c2 = (lane & 3) << 1;
    if (jc == 1) {
#pragma unroll
        for (int dt = 0; dt < 8; dt++) {
            int d = dt * 8 + c2;
            red[r0 * RED_S + d]           = oacc[dt][0];
            red[r0 * RED_S + d + 1]       = oacc[dt][1];
            red[(r0 + 8) * RED_S + d]     = oacc[dt][2];
            red[(r0 + 8) * RED_S + d + 1] = oacc[dt][3];
        }
    }
    __syncthreads();
    if (jc == 0) {
#pragma unroll
        for (int dt = 0; dt < 8; dt++) {
            int d = dt * 8 + c2;
            float2 lo = make_float2(oacc[dt][0] + red[r0 * RED_S + d],
                                    oacc[dt][1] + red[r0 * RED_S + d + 1]);
            float2 hi = make_float2(oacc[dt][2] + red[(r0 + 8) * RED_S + d],
                                    oacc[dt][3] + red[(r0 + 8) * RED_S + d + 1]);
            *(float2*)&dst[(size_t)(n0 + r0) * DIM + d]     = lo;
            *(float2*)&dst[(size_t)(n0 + r0 + 8) * DIM + d] = hi;
        }
    }
}

// ---------------------------------------------------------------------------
// Combine: Out += partial (band half 1)
// ---------------------------------------------------------------------------
__global__ __launch_bounds__(256) void combine_kernel(float* __restrict__ Out)
{
    int i = blockIdx.x * 256 + threadIdx.x;
    float4 a = ((float4*)Out)[i];
    float4 q = ((const float4*)g_P)[i];
    a.x += q.x; a.y += q.y; a.z += q.z; a.w += q.w;
    ((float4*)Out)[i] = a;
}

// ---------------------------------------------------------------------------
extern "C" void kernel_launch(void* const* d_in, const int* in_sizes, int n_in,
                              void* d_out, int out_size)
{
    const float* X  = (const float*)d_in[0];
    const float* Wq = (const float*)d_in[1];
    const float* Wk = (const float*)d_in[2];
    const float* Wv = (const float*)d_in[3];
    float* Out = (float*)d_out;

    cudaFuncSetAttribute(qkv_mma, cudaFuncAttributeMaxDynamicSharedMemorySize,
                         QKV_SMEM);
    cudaFuncSetAttribute(attn_mma, cudaFuncAttributeMaxDynamicSharedMemorySize,
                         ATTN_SMEM);

    prep_w<<<192 * HID / 256, 256>>>(Wq, Wk, Wv);
    prep_coef<<<LSEQ * 32 / 256, 256>>>();
    qkv_mma<<<NTOK / 64, 512, QKV_SMEM>>>(X);
    attn_mma<<<2 * BATCH * (LSEQ / 64), 256, ATTN_SMEM>>>(Out);
    combine_kernel<<<NTOK * DIM / 4 / 256, 256>>>(Out);
}

// round 11
// speedup vs baseline: 5.9923x; 1.2565x over previous
#include <cuda_runtime.h>
#include <cuda_bf16.h>
#include <cuda_fp16.h>
#include <stdint.h>

#define BATCH 2
#define LSEQ  4096
#define HID   1024
#define DIM   64
#define NTOK  (BATCH * LSEQ)
#define LOG2GAMMA (-0.04580368961f)   /* log2(0.96875) */

// ---------------------------------------------------------------------------
// Device globals
// ---------------------------------------------------------------------------
__device__ __nv_bfloat16 g_Qh[NTOK * DIM];
__device__ __nv_bfloat16 g_Ql[NTOK * DIM];
__device__ __nv_bfloat16 g_Kh[NTOK * DIM];
__device__ __nv_bfloat16 g_Kl[NTOK * DIM];
__device__ __nv_bfloat16 g_Vth[NTOK * DIM];       // per-64-tile transposed [t][d][tok]
__device__ __nv_bfloat16 g_Vtl[NTOK * DIM];
__device__ float g_P[NTOK * DIM];                 // partial O from band half 1
__device__ __half g_Whf[192 * HID];               // W^T concat [Q|K|V], fp16
__device__ float4 g_CO[LSEQ * 32];                // xPos coefs (cq,sq,ck,sk)

// ---------------------------------------------------------------------------
// Tensor-core helpers (sm_80+ portable)
// ---------------------------------------------------------------------------
__device__ __forceinline__ uint32_t smem_u32(const void* p) {
    uint32_t a;
    asm("{ .reg .u64 t; cvta.to.shared.u64 t, %1; cvt.u32.u64 %0, t; }"
        : "=r"(a) : "l"(p));
    return a;
}
__device__ __forceinline__ void ldsm4(uint32_t* r, uint32_t addr) {
    asm volatile("ldmatrix.sync.aligned.m8n8.x4.shared.b16 {%0,%1,%2,%3}, [%4];"
                 : "=r"(r[0]), "=r"(r[1]), "=r"(r[2]), "=r"(r[3]) : "r"(addr));
}
__device__ __forceinline__ void mma_bf16(float* d, const uint32_t* a,
                                         uint32_t b0, uint32_t b1) {
    asm volatile(
        "mma.sync.aligned.m16n8k16.row.col.f32.bf16.bf16.f32 "
        "{%0,%1,%2,%3},{%4,%5,%6,%7},{%8,%9},{%0,%1,%2,%3};"
        : "+f"(d[0]), "+f"(d[1]), "+f"(d[2]), "+f"(d[3])
        : "r"(a[0]), "r"(a[1]), "r"(a[2]), "r"(a[3]), "r"(b0), "r"(b1));
}
__device__ __forceinline__ void mma_f16(float* d, const uint32_t* a,
                                        uint32_t b0, uint32_t b1) {
    asm volatile(
        "mma.sync.aligned.m16n8k16.row.col.f32.f16.f16.f32 "
        "{%0,%1,%2,%3},{%4,%5,%6,%7},{%8,%9},{%0,%1,%2,%3};"
        : "+f"(d[0]), "+f"(d[1]), "+f"(d[2]), "+f"(d[3])
        : "r"(a[0]), "r"(a[1]), "r"(a[2]), "r"(a[3]), "r"(b0), "r"(b1));
}
__device__ __forceinline__ uint32_t pack2(__nv_bfloat16 a, __nv_bfloat16 b) {
    __nv_bfloat162 p = __halves2bfloat162(a, b);
    return *(uint32_t*)&p;
}
__device__ __forceinline__ uint32_t pack2h(__half a, __half b) {
    __half2 p = __halves2half2(a, b);
    return *(uint32_t*)&p;
}
__device__ __forceinline__ void cpasync16(uint32_t dst, const void* src) {
    asm volatile("cp.async.cg.shared.global [%0], [%1], 16;"
                 :: "r"(dst), "l"(src));
}
__device__ __forceinline__ void cp_commit() {
    asm volatile("cp.async.commit_group;" ::: "memory");
}
template <int N>
__device__ __forceinline__ void cp_wait() {
    asm volatile("cp.async.wait_group %0;" :: "n"(N) : "memory");
}

// ---------------------------------------------------------------------------
// Prep: W^T concat (192 x 1024) -> fp16, coalesced 32x32 smem transpose
// grid (32, 6), 256 threads
// ---------------------------------------------------------------------------
__global__ __launch_bounds__(256) void prep_w(
    const float* __restrict__ Wq, const float* __restrict__ Wk,
    const float* __restrict__ Wv)
{
    __shared__ float t[32][33];
    const int tx = threadIdx.x & 31, ty = threadIdx.x >> 5;   // ty 0..7
    const int k0 = blockIdx.x * 32;
    const int n0 = blockIdx.y * 32;
    const float* W = (n0 < 64) ? Wq : ((n0 < 128) ? Wk : Wv);
    const int ncol = n0 & 63;
#pragma unroll
    for (int i = 0; i < 4; i++) {
        int k = k0 + ty + i * 8;
        t[ty + i * 8][tx] = W[k * DIM + ncol + tx];
    }
    __syncthreads();
#pragma unroll
    for (int i = 0; i < 4; i++) {
        int n = n0 + ty + i * 8;
        g_Whf[(size_t)n * HID + k0 + tx] = __float2half_rn(t[tx][ty + i * 8]);
    }
}

// ---------------------------------------------------------------------------
// Prep: xPos coefficient table [l][pair i] -> (cq, sq, ck, sk)
// ---------------------------------------------------------------------------
__global__ __launch_bounds__(256) void prep_coef()
{
    int idx = blockIdx.x * 256 + threadIdx.x;
    int l = idx >> 5;
    int i = idx & 31;
    float fl = (float)l;
    float inv_freq = exp2f(-(float)i * (13.287712379549449f / 32.0f));
    float sn, cs;
    sincosf(fl * inv_freq, &sn, &cs);
    float sv = ((float)(2 * i) + 25.6f) / 89.6f;
    float scq = exp2f(fl * (log2f(sv) * (1.0f / 512.0f)));
    g_CO[idx] = make_float4(cs * scq, sn * scq, cs / scq, sn / scq);
}

// ---------------------------------------------------------------------------
// QKV projection, 2-term fp16: X = Xh + Xl (exact), W = fp16(W) single term.
// 512 threads (16 warps, 4x4), warp tile 16x48; K chunks of 64.
// W fp16 double-buffered cp.async; X register-prefetched + converted.
// ---------------------------------------------------------------------------
#define XS    72
#define OXH   0
#define OXL   (OXH + 64 * XS * 2)
#define OW0   (OXL + 64 * XS * 2)                 /* 18432 */
#define OW1   (OW0 + 192 * XS * 2)                /* 46080 */
#define QKV_SMEM (OW1 + 192 * XS * 2)             /* 73728 */

__global__ __launch_bounds__(512, 1) void qkv_mma(const float* __restrict__ X)
{
    extern __shared__ char smem[];
    const uint32_t sb = smem_u32(smem);
    const int tid  = threadIdx.x;
    const int lane = tid & 31;
    const int wid  = tid >> 5;          // 0..15
    const int mr   = (wid >> 2) * 16;
    const int nc   = (wid & 3) * 48;
    const int row0 = blockIdx.x * 64;

    const int xr = tid >> 3;            // 0..63
    const int xc = (tid & 7) << 2;

    const int wn0 = tid >> 3;           // 0..63
    const int wc8 = (tid & 7) << 3;

    float acc[6][4];
#pragma unroll
    for (int b = 0; b < 6; b++)
#pragma unroll
        for (int c = 0; c < 4; c++) acc[b][c] = 0.f;

    // ---- prologue ----
    {
        uint32_t wb = sb + OW0;
#pragma unroll
        for (int it = 0; it < 3; it++) {
            int n = wn0 + it * 64;
            cpasync16(wb + (uint32_t)(n * XS + wc8) * 2, &g_Whf[n * HID + wc8]);
        }
        cp_commit();
#pragma unroll
        for (int it = 0; it < 2; it++) {
            int c = xc + it * 32;
            float4 x = *(const float4*)&X[(size_t)(row0 + xr) * HID + c];
            __half hx = __float2half_rn(x.x);
            __half hy = __float2half_rn(x.y);
            __half hz = __float2half_rn(x.z);
            __half hw = __float2half_rn(x.w);
            uint32_t off = (uint32_t)(xr * XS + c) * 2;
            *(uint2*)(smem + OXH + off) = make_uint2(pack2h(hx, hy), pack2h(hz, hw));
            *(uint2*)(smem + OXL + off) = make_uint2(
                pack2h(__float2half_rn(x.x - __half2float(hx)),
                       __float2half_rn(x.y - __half2float(hy))),
                pack2h(__float2half_rn(x.z - __half2float(hz)),
                       __float2half_rn(x.w - __half2float(hw))));
        }
    }

    for (int ch = 0; ch < 16; ch++) {
        const uint32_t wb = sb + ((ch & 1) ? OW1 : OW0);
        float4 xpre[2];
        if (ch < 15) {
            const int kcn = (ch + 1) * 64;
            uint32_t wbn = sb + ((ch & 1) ? OW0 : OW1);
#pragma unroll
            for (int it = 0; it < 3; it++) {
                int n = wn0 + it * 64;
                cpasync16(wbn + (uint32_t)(n * XS + wc8) * 2,
                          &g_Whf[n * HID + kcn + wc8]);
            }
            cp_commit();
#pragma unroll
            for (int it = 0; it < 2; it++)
                xpre[it] = *(const float4*)&X[(size_t)(row0 + xr) * HID + kcn + xc + it * 32];
            cp_wait<1>();
        } else {
            cp_wait<0>();
        }
        __syncthreads();

        // ---- compute chunk ch: per ks, 5 ldsm + 12 fp16 MMAs ----
        const int lrow = lane & 15;
        const int lcg  = (lane >> 4) << 3;
#pragma unroll
        for (int ks = 0; ks < 4; ks++) {
            const int lcol = ks * 16 + lcg;
            uint32_t ah[4], al[4], bh[3][4];
            {
                uint32_t off = (uint32_t)((mr + lrow) * XS + lcol) * 2;
                ldsm4(ah, sb + OXH + off);
                ldsm4(al, sb + OXL + off);
            }
#pragma unroll
            for (int nf = 0; nf < 3; nf++) {
                uint32_t off = (uint32_t)((nc + nf * 16 + lrow) * XS + lcol) * 2;
                ldsm4(bh[nf], wb + off);
            }
#pragma unroll
            for (int nf = 0; nf < 3; nf++) {
                mma_f16(acc[nf * 2],     ah, bh[nf][0], bh[nf][2]);
                mma_f16(acc[nf * 2],     al, bh[nf][0], bh[nf][2]);
                mma_f16(acc[nf * 2 + 1], ah, bh[nf][1], bh[nf][3]);
                mma_f16(acc[nf * 2 + 1], al, bh[nf][1], bh[nf][3]);
            }
        }
        __syncthreads();

        if (ch < 15) {
#pragma unroll
            for (int it = 0; it < 2; it++) {
                int c = xc + it * 32;
                float4 x = xpre[it];
                __half hx = __float2half_rn(x.x);
                __half hy = __float2half_rn(x.y);
                __half hz = __float2half_rn(x.z);
                __half hw = __float2half_rn(x.w);
                uint32_t off = (uint32_t)(xr * XS + c) * 2;
                *(uint2*)(smem + OXH + off) = make_uint2(pack2h(hx, hy), pack2h(hz, hw));
                *(uint2*)(smem + OXL + off) = make_uint2(
                    pack2h(__float2half_rn(x.x - __half2float(hx)),
                           __float2half_rn(x.y - __half2float(hy))),
                    pack2h(__float2half_rn(x.z - __half2float(hz)),
                           __float2half_rn(x.w - __half2float(hw))));
            }
        }
    }

    // --- Epilogue: xPos + bf16 hi/lo split for Q/K; V transposed hi/lo ---
    const int r4 = lane >> 2;
    const int c2 = (lane & 3) * 2;
#pragma unroll
    for (int h2 = 0; h2 < 2; h2++) {
        int g = row0 + mr + h2 * 8 + r4;
        int l = g & (LSEQ - 1);
#pragma unroll
        for (int nf = 0; nf < 6; nf++) {
            int col0 = nc + nf * 8;
            int mat  = col0 >> 6;
            int lcol = (col0 & 63) + c2;
            float v0 = acc[nf][h2 * 2 + 0];
            float v1 = acc[nf][h2 * 2 + 1];
            if (mat == 0) {
                float4 co = g_CO[l * 32 + (lcol >> 1)];
                float o0 = v0 * co.x - v1 * co.y;
                float o1 = v1 * co.x + v0 * co.y;
                __nv_bfloat16 h0 = __float2bfloat16(o0);
                __nv_bfloat16 h1 = __float2bfloat16(o1);
                *(uint32_t*)&g_Qh[g * DIM + lcol] = pack2(h0, h1);
                *(uint32_t*)&g_Ql[g * DIM + lcol] =
                    pack2(__float2bfloat16(o0 - __bfloat162float(h0)),
                          __float2bfloat16(o1 - __bfloat162float(h1)));
            } else if (mat == 1) {
                float4 co = g_CO[l * 32 + (lcol >> 1)];
                float o0 = v0 * co.z - v1 * co.w;
                float o1 = v1 * co.z + v0 * co.w;
                __nv_bfloat16 h0 = __float2bfloat16(o0);
                __nv_bfloat16 h1 = __float2bfloat16(o1);
                *(uint32_t*)&g_Kh[g * DIM + lcol] = pack2(h0, h1);
                *(uint32_t*)&g_Kl[g * DIM + lcol] =
                    pack2(__float2bfloat16(o0 - __bfloat162float(h0)),
                          __float2bfloat16(o1 - __bfloat162float(h1)));
            } else {
                int t = g >> 6, tok = g & 63;
                __nv_bfloat16 h0 = __float2bfloat16(v0);
                __nv_bfloat16 h1 = __float2bfloat16(v1);
                g_Vth[t * 4096 + lcol * 64 + tok]       = h0;
                g_Vth[t * 4096 + (lcol + 1) * 64 + tok] = h1;
                g_Vtl[t * 4096 + lcol * 64 + tok] =
                    __float2bfloat16(v0 - __bfloat162float(h0));
                g_Vtl[t * 4096 + (lcol + 1) * 64 + tok] =
                    __float2bfloat16(v1 - __bfloat162float(h1));
            }
        }
    }
}

// ---------------------------------------------------------------------------
// Banded decay attention (R8-proven): band 8 tiles, 4+4 split over
// p=0 (-> Out) / p=1 (-> g_P), uniform 3-term bf16. Grid 256, 8 warps.
// ---------------------------------------------------------------------------
#define AS     72
#define OQH_A  0
#define OQL_A  (OQH_A + 64 * AS * 2)
#define OKH_A  (OQL_A + 64 * AS * 2)
#define OKL_A  (OKH_A + 64 * AS * 2)
#define OVH_A  (OKL_A + 64 * AS * 2)
#define OVL_A  (OVH_A + 64 * AS * 2)
#define ATTN_SMEM (OVL_A + 64 * AS * 2)   /* 55296 */
#define RED_S  68

__global__ __launch_bounds__(256) void attn_mma(float* __restrict__ Out)
{
    extern __shared__ char sm[];
    const uint32_t sb = smem_u32(sm);
    const int tid  = threadIdx.x;
    const int lane = tid & 31;
    const int wid  = tid >> 5;
    const int rg   = wid & 3;
    const int jc   = wid >> 2;
    const int p    = blockIdx.x >> 7;
    const int b    = (blockIdx.x >> 6) & 1;
    const int qt   = blockIdx.x & 63;
    const int n0   = b * LSEQ + qt * 64;

    float* __restrict__ dst = p ? g_P : Out;

    int kt0, kt1;
    if (p == 0) { kt0 = qt - 3; if (kt0 < 0) kt0 = 0; kt1 = qt; }
    else        { kt0 = qt - 7; if (kt0 < 0) kt0 = 0; kt1 = qt - 4; }

    if (kt1 < kt0) {
        float4 z = make_float4(0.f, 0.f, 0.f, 0.f);
        for (int t = tid; t < 64 * DIM / 4; t += 256)
            ((float4*)&dst[(size_t)n0 * DIM])[t] = z;
        return;
    }

#pragma unroll
    for (int it = 0; it < 2; it++) {
        int s = it * 256 + tid;
        int r = s >> 3, c8 = (s & 7) << 3;
        uint32_t off = (uint32_t)(r * AS + c8) * 2;
        *(uint4*)(sm + OQH_A + off) = *(const uint4*)&g_Qh[(size_t)(n0 + r) * DIM + c8];
        *(uint4*)(sm + OQL_A + off) = *(const uint4*)&g_Ql[(size_t)(n0 + r) * DIM + c8];
    }

    float oacc[8][4];
#pragma unroll
    for (int d = 0; d < 8; d++)
#pragma unroll
        for (int c = 0; c < 4; c++) oacc[d][c] = 0.f;

    const int r0 = rg * 16 + (lane >> 2);
    const float gi0 = exp2f((float)r0 * LOG2GAMMA);
    const float gi1 = exp2f((float)(r0 + 8) * LOG2GAMMA);
    float gj[4][2];
#pragma unroll
    for (int jt = 0; jt < 4; jt++) {
        int j = jc * 32 + jt * 8 + ((lane & 3) << 1);
        gj[jt][0] = exp2f(-(float)j * LOG2GAMMA);
        gj[jt][1] = exp2f(-(float)(j + 1) * LOG2GAMMA);
    }

    const int lrow = lane & 15;
    const int lcg  = (lane >> 4) << 3;

    for (int kt = kt0; kt <= kt1; kt++) {
        const int m0 = b * LSEQ + kt * 64;
        const int tile = m0 >> 6;
        __syncthreads();
#pragma unroll
        for (int it = 0; it < 2; it++) {
            int s = it * 256 + tid;
            int r = s >> 3, c8 = (s & 7) << 3;
            uint32_t off = (uint32_t)(r * AS + c8) * 2;
            *(uint4*)(sm + OKH_A + off) = *(const uint4*)&g_Kh[(size_t)(m0 + r) * DIM + c8];
            *(uint4*)(sm + OKL_A + off) = *(const uint4*)&g_Kl[(size_t)(m0 + r) * DIM + c8];
            *(uint4*)(sm + OVH_A + off) = *(const uint4*)&g_Vth[(size_t)tile * 4096 + r * 64 + c8];
            *(uint4*)(sm + OVL_A + off) = *(const uint4*)&g_Vtl[(size_t)tile * 4096 + r * 64 + c8];
        }
        __syncthreads();

        float sfrag[4][4];
#pragma unroll
        for (int jt = 0; jt < 4; jt++)
#pragma unroll
            for (int c = 0; c < 4; c++) sfrag[jt][c] = 0.f;

#pragma unroll
        for (int ks = 0; ks < 4; ks++) {
            uint32_t aoff = (uint32_t)((rg * 16 + lrow) * AS + ks * 16 + lcg) * 2;
            uint32_t ah[4], al[4];
            ldsm4(ah, sb + OQH_A + aoff);
            ldsm4(al, sb + OQL_A + aoff);
            uint32_t bh[2][4], bl[2][4];
#pragma unroll
            for (int jg = 0; jg < 2; jg++) {
                uint32_t boff = (uint32_t)((jc * 32 + jg * 16 + lrow) * AS + ks * 16 + lcg) * 2;
                ldsm4(bh[jg], sb + OKH_A + boff);
                ldsm4(bl[jg], sb + OKL_A + boff);
            }
#pragma unroll
            for (int jt = 0; jt < 4; jt++) {
                int jg = jt >> 1, sel = jt & 1;
                uint32_t b0h = bh[jg][sel], b1h = bh[jg][sel + 2];
                uint32_t b0l = bl[jg][sel], b1l = bl[jg][sel + 2];
                mma_bf16(sfrag[jt], ah, b0h, b1h);
                mma_bf16(sfrag[jt], ah, b0l, b1l);
                mma_bf16(sfrag[jt], al, b0h, b1h);
            }
        }

        const float basekt = exp2f((float)((qt - kt) * 64) * LOG2GAMMA);
        uint32_t shh[2][4], sll[2][4];
#pragma unroll
        for (int jt = 0; jt < 4; jt++) {
            float w0 = basekt * gj[jt][0];
            float w1 = basekt * gj[jt][1];
            float v0 = sfrag[jt][0] * gi0 * w0;
            float v1 = sfrag[jt][1] * gi0 * w1;
            float v2 = sfrag[jt][2] * gi1 * w0;
            float v3 = sfrag[jt][3] * gi1 * w1;
            if (kt == qt) {
                int j0 = jc * 32 + jt * 8 + ((lane & 3) << 1);
                if (r0 < j0)         v0 = 0.f;
                if (r0 < j0 + 1)     v1 = 0.f;
                if (r0 + 8 < j0)     v2 = 0.f;
                if (r0 + 8 < j0 + 1) v3 = 0.f;
            }
            __nv_bfloat16 h0 = __float2bfloat16(v0);
            __nv_bfloat16 h1 = __float2bfloat16(v1);
            __nv_bfloat16 h2 = __float2bfloat16(v2);
            __nv_bfloat16 h3 = __float2bfloat16(v3);
            int ks2 = jt >> 1, odd = jt & 1;
            shh[ks2][odd * 2 + 0] = pack2(h0, h1);
            shh[ks2][odd * 2 + 1] = pack2(h2, h3);
            sll[ks2][odd * 2 + 0] =
                pack2(__float2bfloat16(v0 - __bfloat162float(h0)),
                      __float2bfloat16(v1 - __bfloat162float(h1)));
            sll[ks2][odd * 2 + 1] =
                pack2(__float2bfloat16(v2 - __bfloat162float(h2)),
                      __float2bfloat16(v3 - __bfloat162float(h3)));
        }

#pragma unroll
        for (int ks2 = 0; ks2 < 2; ks2++) {
            uint32_t vbh[4][4], vbl[4][4];
#pragma unroll
            for (int dg = 0; dg < 4; dg++) {
                uint32_t voff = (uint32_t)((dg * 16 + lrow) * AS + jc * 32 + ks2 * 16 + lcg) * 2;
                ldsm4(vbh[dg], sb + OVH_A + voff);
                ldsm4(vbl[dg], sb + OVL_A + voff);
            }
#pragma unroll
            for (int dt = 0; dt < 8; dt++) {
                int dg = dt >> 1, sel = dt & 1;
                uint32_t b0h = vbh[dg][sel], b1h = vbh[dg][sel + 2];
                uint32_t b0l = vbl[dg][sel], b1l = vbl[dg][sel + 2];
                mma_bf16(oacc[dt], shh[ks2], b0h, b1h);
                mma_bf16(oacc[dt], sll[ks2], b0h, b1h);
                mma_bf16(oacc[dt], shh[ks2], b0l, b1l);
            }
        }
    }

    __syncthreads();
    float* red = (float*)sm;
    const int c2 = (lane & 3) << 1;
    if (jc == 1) {
#pragma unroll
        for (int dt = 0; dt < 8; dt++) {
            int d = dt * 8 + c2;
            red[r0 * RED_S + d]           = oacc[dt][0];
            red[r0 * RED_S + d + 1]       = oacc[dt][1];
            red[(r0 + 8) * RED_S + d]     = oacc[dt][2];
            red[(r0 + 8) * RED_S + d + 1] = oacc[dt][3];
        }
    }
    __syncthreads();
    if (jc == 0) {
#pragma unroll
        for (int dt = 0; dt < 8; dt++) {
            int d = dt * 8 + c2;
            float2 lo = make_float2(oacc[dt][0] + red[r0 * RED_S + d],
                                    oacc[dt][1] + red[r0 * RED_S + d + 1]);
            float2 hi = make_float2(oacc[dt][2] + red[(r0 + 8) * RED_S + d],
                                    oacc[dt][3] + red[(r0 + 8) * RED_S + d + 1]);
            *(float2*)&dst[(size_t)(n0 + r0) * DIM + d]     = lo;
            *(float2*)&dst[(size_t)(n0 + r0 + 8) * DIM + d] = hi;
        }
    }
}

// ---------------------------------------------------------------------------
// Combine: Out += partial (band half 1)
// ---------------------------------------------------------------------------
__global__ __launch_bounds__(256) void combine_kernel(float* __restrict__ Out)
{
    int i = blockIdx.x * 256 + threadIdx.x;
    float4 a = ((float4*)Out)[i];
    float4 q = ((const float4*)g_P)[i];
    a.x += q.x; a.y += q.y; a.z += q.z; a.w += q.w;
    ((float4*)Out)[i] = a;
}

// ---------------------------------------------------------------------------
extern "C" void kernel_launch(void* const* d_in, const int* in_sizes, int n_in,
                              void* d_out, int out_size)
{
    const float* X  = (const float*)d_in[0];
    const float* Wq = (const float*)d_in[1];
    const float* Wk = (const float*)d_in[2];
    const float* Wv = (const float*)d_in[3];
    float* Out = (float*)d_out;

    cudaFuncSetAttribute(qkv_mma, cudaFuncAttributeMaxDynamicSharedMemorySize,
                         QKV_SMEM);
    cudaFuncSetAttribute(attn_mma, cudaFuncAttributeMaxDynamicSharedMemorySize,
                         ATTN_SMEM);

    prep_w<<<dim3(32, 6), 256>>>(Wq, Wk, Wv);
    prep_coef<<<LSEQ * 32 / 256, 256>>>();
    qkv_mma<<<NTOK / 64, 512, QKV_SMEM>>>(X);
    attn_mma<<<2 * BATCH * (LSEQ / 64), 256, ATTN_SMEM>>>(Out);
    combine_kernel<<<NTOK * DIM / 4 / 256, 256>>>(Out);
}

// round 12
// speedup vs baseline: 6.4881x; 1.0827x over previous
#include <cuda_runtime.h>
#include <cuda_bf16.h>
#include <cuda_fp16.h>
#include <stdint.h>

#define BATCH 2
#define LSEQ  4096
#define HID   1024
#define DIM   64
#define NTOK  (BATCH * LSEQ)
#define LOG2GAMMA (-0.04580368961f)   /* log2(0.96875) */

// ---------------------------------------------------------------------------
// Device globals
// ---------------------------------------------------------------------------
__device__ __nv_bfloat16 g_Qh[NTOK * DIM];
__device__ __nv_bfloat16 g_Ql[NTOK * DIM];
__device__ __nv_bfloat16 g_Kh[NTOK * DIM];
__device__ __nv_bfloat16 g_Kl[NTOK * DIM];
__device__ __nv_bfloat16 g_Vth[NTOK * DIM];       // per-64-tile transposed [t][d][tok]
__device__ __nv_bfloat16 g_Vtl[NTOK * DIM];
__device__ float g_P[NTOK * DIM];                 // partial O from band half 1
__device__ __half g_Whf[192 * HID];               // W^T concat [Q|K|V], fp16
__device__ float4 g_CO[LSEQ * 32];                // xPos coefs (cq,sq,ck,sk)

// ---------------------------------------------------------------------------
// Tensor-core helpers (sm_80+ portable)
// ---------------------------------------------------------------------------
__device__ __forceinline__ uint32_t smem_u32(const void* p) {
    uint32_t a;
    asm("{ .reg .u64 t; cvta.to.shared.u64 t, %1; cvt.u32.u64 %0, t; }"
        : "=r"(a) : "l"(p));
    return a;
}
__device__ __forceinline__ void ldsm4(uint32_t* r, uint32_t addr) {
    asm volatile("ldmatrix.sync.aligned.m8n8.x4.shared.b16 {%0,%1,%2,%3}, [%4];"
                 : "=r"(r[0]), "=r"(r[1]), "=r"(r[2]), "=r"(r[3]) : "r"(addr));
}
__device__ __forceinline__ void mma_bf16(float* d, const uint32_t* a,
                                         uint32_t b0, uint32_t b1) {
    asm volatile(
        "mma.sync.aligned.m16n8k16.row.col.f32.bf16.bf16.f32 "
        "{%0,%1,%2,%3},{%4,%5,%6,%7},{%8,%9},{%0,%1,%2,%3};"
        : "+f"(d[0]), "+f"(d[1]), "+f"(d[2]), "+f"(d[3])
        : "r"(a[0]), "r"(a[1]), "r"(a[2]), "r"(a[3]), "r"(b0), "r"(b1));
}
__device__ __forceinline__ void mma_f16(float* d, const uint32_t* a,
                                        uint32_t b0, uint32_t b1) {
    asm volatile(
        "mma.sync.aligned.m16n8k16.row.col.f32.f16.f16.f32 "
        "{%0,%1,%2,%3},{%4,%5,%6,%7},{%8,%9},{%0,%1,%2,%3};"
        : "+f"(d[0]), "+f"(d[1]), "+f"(d[2]), "+f"(d[3])
        : "r"(a[0]), "r"(a[1]), "r"(a[2]), "r"(a[3]), "r"(b0), "r"(b1));
}
__device__ __forceinline__ uint32_t pack2(__nv_bfloat16 a, __nv_bfloat16 b) {
    __nv_bfloat162 p = __halves2bfloat162(a, b);
    return *(uint32_t*)&p;
}
__device__ __forceinline__ uint32_t pack2h(__half a, __half b) {
    __half2 p = __halves2half2(a, b);
    return *(uint32_t*)&p;
}
__device__ __forceinline__ void cpasync16(uint32_t dst, const void* src) {
    asm volatile("cp.async.cg.shared.global [%0], [%1], 16;"
                 :: "r"(dst), "l"(src));
}
__device__ __forceinline__ void cp_commit() {
    asm volatile("cp.async.commit_group;" ::: "memory");
}
template <int N>
__device__ __forceinline__ void cp_wait() {
    asm volatile("cp.async.wait_group %0;" :: "n"(N) : "memory");
}

// ---------------------------------------------------------------------------
// Merged prep kernel.
//  blocks [0,192):   W^T concat -> fp16, coalesced 32x32 smem transpose
//  blocks [192,704): xPos coefficient table
// ---------------------------------------------------------------------------
__global__ __launch_bounds__(256) void prep_all(
    const float* __restrict__ Wq, const float* __restrict__ Wk,
    const float* __restrict__ Wv)
{
    __shared__ float t[32][33];
    if (blockIdx.x < 192) {
        const int tx = threadIdx.x & 31, ty = threadIdx.x >> 5;
        const int k0 = (blockIdx.x & 31) * 32;
        const int n0 = (blockIdx.x >> 5) * 32;
        const float* W = (n0 < 64) ? Wq : ((n0 < 128) ? Wk : Wv);
        const int ncol = n0 & 63;
#pragma unroll
        for (int i = 0; i < 4; i++) {
            int k = k0 + ty + i * 8;
            t[ty + i * 8][tx] = W[k * DIM + ncol + tx];
        }
        __syncthreads();
#pragma unroll
        for (int i = 0; i < 4; i++) {
            int n = n0 + ty + i * 8;
            g_Whf[(size_t)n * HID + k0 + tx] = __float2half_rn(t[tx][ty + i * 8]);
        }
    } else {
        int idx = (blockIdx.x - 192) * 256 + threadIdx.x;
        int l = idx >> 5;
        int i = idx & 31;
        float fl = (float)l;
        float inv_freq = exp2f(-(float)i * (13.287712379549449f / 32.0f));
        float sn, cs;
        sincosf(fl * inv_freq, &sn, &cs);
        float sv = ((float)(2 * i) + 25.6f) / 89.6f;
        float scq = exp2f(fl * (log2f(sv) * (1.0f / 512.0f)));
        g_CO[idx] = make_float4(cs * scq, sn * scq, cs / scq, sn / scq);
    }
}

// ---------------------------------------------------------------------------
// QKV projection, 2-term fp16 (X = Xh + Xl exact; W = fp16 single term).
// 512 threads (16 warps, 4x4), warp tile 16x48; K chunks of 64.
// X double-buffered in smem (register prefetch + convert) and W fp16
// double-buffered via cp.async -> ONE __syncthreads per chunk.
// ---------------------------------------------------------------------------
#define XS    72
#define XBUF  (2 * 64 * XS * 2)                   /* 18432: hi + lo */
#define OXL   (64 * XS * 2)                       /* lo offset within X buf */
#define OW    (2 * XBUF)                          /* 36864 */
#define WBUF  (192 * XS * 2)                      /* 27648 */
#define QKV_SMEM (OW + 2 * WBUF)                  /* 92160 */

__global__ __launch_bounds__(512, 1) void qkv_mma(const float* __restrict__ X)
{
    extern __shared__ char smem[];
    const uint32_t sb = smem_u32(smem);
    const int tid  = threadIdx.x;
    const int lane = tid & 31;
    const int wid  = tid >> 5;          // 0..15
    const int mr   = (wid >> 2) * 16;
    const int nc   = (wid & 3) * 48;
    const int row0 = blockIdx.x * 64;

    const int xr = tid >> 3;            // 0..63
    const int xc = (tid & 7) << 2;

    const int wn0 = tid >> 3;           // 0..63
    const int wc8 = (tid & 7) << 3;

    float acc[6][4];
#pragma unroll
    for (int b = 0; b < 6; b++)
#pragma unroll
        for (int c = 0; c < 4; c++) acc[b][c] = 0.f;

    // ---- prologue: W0 via cp.async; X0 LDG + convert into xbuf0 ----
    {
#pragma unroll
        for (int it = 0; it < 3; it++) {
            int n = wn0 + it * 64;
            cpasync16(sb + OW + (uint32_t)(n * XS + wc8) * 2, &g_Whf[n * HID + wc8]);
        }
        cp_commit();
#pragma unroll
        for (int it = 0; it < 2; it++) {
            int c = xc + it * 32;
            float4 x = *(const float4*)&X[(size_t)(row0 + xr) * HID + c];
            __half hx = __float2half_rn(x.x);
            __half hy = __float2half_rn(x.y);
            __half hz = __float2half_rn(x.z);
            __half hw = __float2half_rn(x.w);
            uint32_t off = (uint32_t)(xr * XS + c) * 2;
            *(uint2*)(smem + off)       = make_uint2(pack2h(hx, hy), pack2h(hz, hw));
            *(uint2*)(smem + OXL + off) = make_uint2(
                pack2h(__float2half_rn(x.x - __half2float(hx)),
                       __float2half_rn(x.y - __half2float(hy))),
                pack2h(__float2half_rn(x.z - __half2float(hz)),
                       __float2half_rn(x.w - __half2float(hw))));
        }
    }

    for (int ch = 0; ch < 16; ch++) {
        const uint32_t xb = sb + (uint32_t)(ch & 1) * XBUF;
        const uint32_t wb = sb + OW + (uint32_t)(ch & 1) * WBUF;
        cp_wait<0>();
        __syncthreads();

        float4 xpre[2];
        if (ch < 15) {
            const int kcn = (ch + 1) * 64;
            uint32_t wbn = sb + OW + (uint32_t)((ch + 1) & 1) * WBUF;
#pragma unroll
            for (int it = 0; it < 3; it++) {
                int n = wn0 + it * 64;
                cpasync16(wbn + (uint32_t)(n * XS + wc8) * 2,
                          &g_Whf[n * HID + kcn + wc8]);
            }
            cp_commit();
#pragma unroll
            for (int it = 0; it < 2; it++)
                xpre[it] = *(const float4*)&X[(size_t)(row0 + xr) * HID + kcn + xc + it * 32];
        }

        // ---- compute chunk ch: per ks, 5 ldsm + 12 fp16 MMAs ----
        const int lrow = lane & 15;
        const int lcg  = (lane >> 4) << 3;
#pragma unroll
        for (int ks = 0; ks < 4; ks++) {
            const int lcol = ks * 16 + lcg;
            uint32_t ah[4], al[4], bh[3][4];
            {
                uint32_t off = (uint32_t)((mr + lrow) * XS + lcol) * 2;
                ldsm4(ah, xb + off);
                ldsm4(al, xb + OXL + off);
            }
#pragma unroll
            for (int nf = 0; nf < 3; nf++) {
                uint32_t off = (uint32_t)((nc + nf * 16 + lrow) * XS + lcol) * 2;
                ldsm4(bh[nf], wb + off);
            }
#pragma unroll
            for (int nf = 0; nf < 3; nf++) {
                mma_f16(acc[nf * 2],     ah, bh[nf][0], bh[nf][2]);
                mma_f16(acc[nf * 2],     al, bh[nf][0], bh[nf][2]);
                mma_f16(acc[nf * 2 + 1], ah, bh[nf][1], bh[nf][3]);
                mma_f16(acc[nf * 2 + 1], al, bh[nf][1], bh[nf][3]);
            }
        }

        // ---- convert prefetched X -> other xbuf (guarded by next sync) ----
        if (ch < 15) {
            char* xdn = smem + (size_t)((ch + 1) & 1) * XBUF;
#pragma unroll
            for (int it = 0; it < 2; it++) {
                int c = xc + it * 32;
                float4 x = xpre[it];
                __half hx = __float2half_rn(x.x);
                __half hy = __float2half_rn(x.y);
                __half hz = __float2half_rn(x.z);
                __half hw = __float2half_rn(x.w);
                uint32_t off = (uint32_t)(xr * XS + c) * 2;
                *(uint2*)(xdn + off)       = make_uint2(pack2h(hx, hy), pack2h(hz, hw));
                *(uint2*)(xdn + OXL + off) = make_uint2(
                    pack2h(__float2half_rn(x.x - __half2float(hx)),
                           __float2half_rn(x.y - __half2float(hy))),
                    pack2h(__float2half_rn(x.z - __half2float(hz)),
                           __float2half_rn(x.w - __half2float(hw))));
            }
        }
    }

    // --- Epilogue: xPos + bf16 hi/lo split for Q/K; V transposed hi/lo ---
    const int r4 = lane >> 2;
    const int c2 = (lane & 3) * 2;
#pragma unroll
    for (int h2 = 0; h2 < 2; h2++) {
        int g = row0 + mr + h2 * 8 + r4;
        int l = g & (LSEQ - 1);
#pragma unroll
        for (int nf = 0; nf < 6; nf++) {
            int col0 = nc + nf * 8;
            int mat  = col0 >> 6;
            int lcol = (col0 & 63) + c2;
            float v0 = acc[nf][h2 * 2 + 0];
            float v1 = acc[nf][h2 * 2 + 1];
            if (mat == 0) {
                float4 co = g_CO[l * 32 + (lcol >> 1)];
                float o0 = v0 * co.x - v1 * co.y;
                float o1 = v1 * co.x + v0 * co.y;
                __nv_bfloat16 h0 = __float2bfloat16(o0);
                __nv_bfloat16 h1 = __float2bfloat16(o1);
                *(uint32_t*)&g_Qh[g * DIM + lcol] = pack2(h0, h1);
                *(uint32_t*)&g_Ql[g * DIM + lcol] =
                    pack2(__float2bfloat16(o0 - __bfloat162float(h0)),
                          __float2bfloat16(o1 - __bfloat162float(h1)));
            } else if (mat == 1) {
                float4 co = g_CO[l * 32 + (lcol >> 1)];
                float o0 = v0 * co.z - v1 * co.w;
                float o1 = v1 * co.z + v0 * co.w;
                __nv_bfloat16 h0 = __float2bfloat16(o0);
                __nv_bfloat16 h1 = __float2bfloat16(o1);
                *(uint32_t*)&g_Kh[g * DIM + lcol] = pack2(h0, h1);
                *(uint32_t*)&g_Kl[g * DIM + lcol] =
                    pack2(__float2bfloat16(o0 - __bfloat162float(h0)),
                          __float2bfloat16(o1 - __bfloat162float(h1)));
            } else {
                int t = g >> 6, tok = g & 63;
                __nv_bfloat16 h0 = __float2bfloat16(v0);
                __nv_bfloat16 h1 = __float2bfloat16(v1);
                g_Vth[t * 4096 + lcol * 64 + tok]       = h0;
                g_Vth[t * 4096 + (lcol + 1) * 64 + tok] = h1;
                g_Vtl[t * 4096 + lcol * 64 + tok] =
                    __float2bfloat16(v0 - __bfloat162float(h0));
                g_Vtl[t * 4096 + (lcol + 1) * 64 + tok] =
                    __float2bfloat16(v1 - __bfloat162float(h1));
            }
        }
    }
}

// ---------------------------------------------------------------------------
// Banded decay attention (R8 numerics), cp.async double-buffered kt pipeline.
// Band 8 tiles, 4+4 split p=0 (-> Out) / p=1 (-> g_P), 3-term bf16.
// Grid 256, 8 warps. One __syncthreads per kt.
// ---------------------------------------------------------------------------
#define AS     72
#define TILE_B (64 * AS * 2)               /* 9216 */
#define OQH_A  0
#define OQL_A  TILE_B
#define OKV    (2 * TILE_B)                /* 18432: start of kv double buffer */
#define KVBUF  (4 * TILE_B)                /* 36864: KH, KL, VH, VL */
#define OFF_KH 0
#define OFF_KL TILE_B
#define OFF_VH (2 * TILE_B)
#define OFF_VL (3 * TILE_B)
#define ATTN_SMEM (OKV + 2 * KVBUF)        /* 92160 */
#define RED_S  68

__device__ __forceinline__ void attn_prefetch_kv(
    uint32_t kvb, int m0, int tile, int tid)
{
#pragma unroll
    for (int it = 0; it < 2; it++) {
        int s = it * 256 + tid;
        int r = s >> 3, c8 = (s & 7) << 3;
        uint32_t off = (uint32_t)(r * AS + c8) * 2;
        cpasync16(kvb + OFF_KH + off, &g_Kh[(size_t)(m0 + r) * DIM + c8]);
        cpasync16(kvb + OFF_KL + off, &g_Kl[(size_t)(m0 + r) * DIM + c8]);
        cpasync16(kvb + OFF_VH + off, &g_Vth[(size_t)tile * 4096 + r * 64 + c8]);
        cpasync16(kvb + OFF_VL + off, &g_Vtl[(size_t)tile * 4096 + r * 64 + c8]);
    }
    cp_commit();
}

__global__ __launch_bounds__(256) void attn_mma(float* __restrict__ Out)
{
    extern __shared__ char sm[];
    const uint32_t sb = smem_u32(sm);
    const int tid  = threadIdx.x;
    const int lane = tid & 31;
    const int wid  = tid >> 5;
    const int rg   = wid & 3;
    const int jc   = wid >> 2;
    const int p    = blockIdx.x >> 7;
    const int b    = (blockIdx.x >> 6) & 1;
    const int qt   = blockIdx.x & 63;
    const int n0   = b * LSEQ + qt * 64;

    float* __restrict__ dst = p ? g_P : Out;

    int kt0, kt1;
    if (p == 0) { kt0 = qt - 3; if (kt0 < 0) kt0 = 0; kt1 = qt; }
    else        { kt0 = qt - 7; if (kt0 < 0) kt0 = 0; kt1 = qt - 4; }

    if (kt1 < kt0) {
        float4 z = make_float4(0.f, 0.f, 0.f, 0.f);
        for (int t = tid; t < 64 * DIM / 4; t += 256)
            ((float4*)&dst[(size_t)n0 * DIM])[t] = z;
        return;
    }

    // Q tiles (plain LDG/STS; covered by first sync)
#pragma unroll
    for (int it = 0; it < 2; it++) {
        int s = it * 256 + tid;
        int r = s >> 3, c8 = (s & 7) << 3;
        uint32_t off = (uint32_t)(r * AS + c8) * 2;
        *(uint4*)(sm + OQH_A + off) = *(const uint4*)&g_Qh[(size_t)(n0 + r) * DIM + c8];
        *(uint4*)(sm + OQL_A + off) = *(const uint4*)&g_Ql[(size_t)(n0 + r) * DIM + c8];
    }

    // prologue: prefetch kt0 tiles into buf0
    {
        const int m0 = b * LSEQ + kt0 * 64;
        attn_prefetch_kv(sb + OKV, m0, m0 >> 6, tid);
    }

    float oacc[8][4];
#pragma unroll
    for (int d = 0; d < 8; d++)
#pragma unroll
        for (int c = 0; c < 4; c++) oacc[d][c] = 0.f;

    const int r0 = rg * 16 + (lane >> 2);
    const float gi0 = exp2f((float)r0 * LOG2GAMMA);
    const float gi1 = exp2f((float)(r0 + 8) * LOG2GAMMA);
    float gj[4][2];
#pragma unroll
    for (int jt = 0; jt < 4; jt++) {
        int j = jc * 32 + jt * 8 + ((lane & 3) << 1);
        gj[jt][0] = exp2f(-(float)j * LOG2GAMMA);
        gj[jt][1] = exp2f(-(float)(j + 1) * LOG2GAMMA);
    }

    const int lrow = lane & 15;
    const int lcg  = (lane >> 4) << 3;

    for (int kt = kt0; kt <= kt1; kt++) {
        const uint32_t kvb = sb + OKV + (uint32_t)((kt - kt0) & 1) * KVBUF;
        cp_wait<0>();
        __syncthreads();
        if (kt < kt1) {
            const int m0n = b * LSEQ + (kt + 1) * 64;
            attn_prefetch_kv(sb + OKV + (uint32_t)((kt - kt0 + 1) & 1) * KVBUF,
                             m0n, m0n >> 6, tid);
        }

        // ---- S = Q K^T (3-term) ----
        float sfrag[4][4];
#pragma unroll
        for (int jt = 0; jt < 4; jt++)
#pragma unroll
            for (int c = 0; c < 4; c++) sfrag[jt][c] = 0.f;

#pragma unroll
        for (int ks = 0; ks < 4; ks++) {
            uint32_t aoff = (uint32_t)((rg * 16 + lrow) * AS + ks * 16 + lcg) * 2;
            uint32_t ah[4], al[4];
            ldsm4(ah, sb + OQH_A + aoff);
            ldsm4(al, sb + OQL_A + aoff);
            uint32_t bh[2][4], bl[2][4];
#pragma unroll
            for (int jg = 0; jg < 2; jg++) {
                uint32_t boff = (uint32_t)((jc * 32 + jg * 16 + lrow) * AS + ks * 16 + lcg) * 2;
                ldsm4(bh[jg], kvb + OFF_KH + boff);
                ldsm4(bl[jg], kvb + OFF_KL + boff);
            }
#pragma unroll
            for (int jt = 0; jt < 4; jt++) {
                int jg = jt >> 1, sel = jt & 1;
                uint32_t b0h = bh[jg][sel], b1h = bh[jg][sel + 2];
                uint32_t b0l = bl[jg][sel], b1l = bl[jg][sel + 2];
                mma_bf16(sfrag[jt], ah, b0h, b1h);
                mma_bf16(sfrag[jt], ah, b0l, b1l);
                mma_bf16(sfrag[jt], al, b0h, b1h);
            }
        }

        // ---- decay + mask + frag-direct hi/lo conversion ----
        const float basekt = exp2f((float)((qt - kt) * 64) * LOG2GAMMA);
        uint32_t shh[2][4], sll[2][4];
#pragma unroll
        for (int jt = 0; jt < 4; jt++) {
            float w0 = basekt * gj[jt][0];
            float w1 = basekt * gj[jt][1];
            float v0 = sfrag[jt][0] * gi0 * w0;
            float v1 = sfrag[jt][1] * gi0 * w1;
            float v2 = sfrag[jt][2] * gi1 * w0;
            float v3 = sfrag[jt][3] * gi1 * w1;
            if (kt == qt) {
                int j0 = jc * 32 + jt * 8 + ((lane & 3) << 1);
                if (r0 < j0)         v0 = 0.f;
                if (r0 < j0 + 1)     v1 = 0.f;
                if (r0 + 8 < j0)     v2 = 0.f;
                if (r0 + 8 < j0 + 1) v3 = 0.f;
            }
            __nv_bfloat16 h0 = __float2bfloat16(v0);
            __nv_bfloat16 h1 = __float2bfloat16(v1);
            __nv_bfloat16 h2 = __float2bfloat16(v2);
            __nv_bfloat16 h3 = __float2bfloat16(v3);
            int ks2 = jt >> 1, odd = jt & 1;
            shh[ks2][odd * 2 + 0] = pack2(h0, h1);
            shh[ks2][odd * 2 + 1] = pack2(h2, h3);
            sll[ks2][odd * 2 + 0] =
                pack2(__float2bfloat16(v0 - __bfloat162float(h0)),
                      __float2bfloat16(v1 - __bfloat162float(h1)));
            sll[ks2][odd * 2 + 1] =
                pack2(__float2bfloat16(v2 - __bfloat162float(h2)),
                      __float2bfloat16(v3 - __bfloat162float(h3)));
        }

        // ---- O += S V (3-term) ----
#pragma unroll
        for (int ks2 = 0; ks2 < 2; ks2++) {
            uint32_t vbh[4][4], vbl[4][4];
#pragma unroll
            for (int dg = 0; dg < 4; dg++) {
                uint32_t voff = (uint32_t)((dg * 16 + lrow) * AS + jc * 32 + ks2 * 16 + lcg) * 2;
                ldsm4(vbh[dg], kvb + OFF_VH + voff);
                ldsm4(vbl[dg], kvb + OFF_VL + voff);
            }
#pragma unroll
            for (int dt = 0; dt < 8; dt++) {
                int dg = dt >> 1, sel = dt & 1;
                uint32_t b0h = vbh[dg][sel], b1h = vbh[dg][sel + 2];
                uint32_t b0l = vbl[dg][sel], b1l = vbl[dg][sel + 2];
                mma_bf16(oacc[dt], shh[ks2], b0h, b1h);
                mma_bf16(oacc[dt], sll[ks2], b0h, b1h);
                mma_bf16(oacc[dt], shh[ks2], b0l, b1l);
            }
        }
    }

    // ---- pair reduction (w, w+4) over smem, then store ----
    __syncthreads();
    float* red = (float*)sm;                 // reuses Q area
    const int c2 = (lane & 3) << 1;
    if (jc == 1) {
#pragma unroll
        for (int dt = 0; dt < 8; dt++) {
            int d = dt * 8 + c2;
            red[r0 * RED_S + d]           = oacc[dt][0];
            red[r0 * RED_S + d + 1]       = oacc[dt][1];
            red[(r0 + 8) * RED_S + d]     = oacc[dt][2];
            red[(r0 + 8) * RED_S + d + 1] = oacc[dt][3];
        }
    }
    __syncthreads();
    if (jc == 0) {
#pragma unroll
        for (int dt = 0; dt < 8; dt++) {
            int d = dt * 8 + c2;
            float2 lo = make_float2(oacc[dt][0] + red[r0 * RED_S + d],
                                    oacc[dt][1] + red[r0 * RED_S + d + 1]);
            float2 hi = make_float2(oacc[dt][2] + red[(r0 + 8) * RED_S + d],
                                    oacc[dt][3] + red[(r0 + 8) * RED_S + d + 1]);
            *(float2*)&dst[(size_t)(n0 + r0) * DIM + d]     = lo;
            *(float2*)&dst[(size_t)(n0 + r0 + 8) * DIM + d] = hi;
        }
    }
}

// ---------------------------------------------------------------------------
// Combine: Out += partial (band half 1)
// ---------------------------------------------------------------------------
__global__ __launch_bounds__(256) void combine_kernel(float* __restrict__ Out)
{
    int i = blockIdx.x * 256 + threadIdx.x;
    float4 a = ((float4*)Out)[i];
    float4 q = ((const float4*)g_P)[i];
    a.x += q.x; a.y += q.y; a.z += q.z; a.w += q.w;
    ((float4*)Out)[i] = a;
}

// ---------------------------------------------------------------------------
extern "C" void kernel_launch(void* const* d_in, const int* in_sizes, int n_in,
                              void* d_out, int out_size)
{
    const float* X  = (const float*)d_in[0];
    const float* Wq = (const float*)d_in[1];
    const float* Wk = (const float*)d_in[2];
    const float* Wv = (const float*)d_in[3];
    float* Out = (float*)d_out;

    cudaFuncSetAttribute(qkv_mma, cudaFuncAttributeMaxDynamicSharedMemorySize,
                         QKV_SMEM);
    cudaFuncSetAttribute(attn_mma, cudaFuncAttributeMaxDynamicSharedMemorySize,
                         ATTN_SMEM);

    prep_all<<<704, 256>>>(Wq, Wk, Wv);
    qkv_mma<<<NTOK / 64, 512, QKV_SMEM>>>(X);
    attn_mma<<<2 * BATCH * (LSEQ / 64), 256, ATTN_SMEM>>>(Out);
    combine_kernel<<<NTOK * DIM / 4 / 256, 256>>>(Out);
}